// round 10
// baseline (speedup 1.0000x reference)
#include <cuda_runtime.h>
#include <cuda_fp16.h>
#include <cstdint>

// ---------------- problem constants ----------------------------------------
#define NN   100000   // batch rows
#define NNP  100096   // padded to 128
#define D_IN 500      // input features
#define KP1  512      // D_IN padded to MMA K granularity
#define HF   256      // hidden
#define MM   50000    // cluster rows
#define MMP  50048    // padded to 128
#define KC   40       // clusters
#define O2   1024     // OUT*OUT
#define EPSV 1e-5f

static inline int cdiv_h(int a, int b) { return (a + b - 1) / b; }

// ---------------- device scratch --------------------------------------------
__device__ float g_H1[(size_t)NN * HF];
__device__ float g_H2[(size_t)NN * HF];
__device__ float g_XC[(size_t)MM * HF];
__device__ float g_sum1[HF], g_sq1[HF], g_a1[HF], g_c1[HF];
__device__ float g_sum2[HF], g_sq2[HF], g_a2[HF], g_c2[HF];
__device__ float g_CFsum[KC * HF];
__device__ int   g_counts[KC];
__device__ int   g_labels[MM];
__device__ float g_PA[KC * O2];
__device__ float g_PB[KC * O2];

// Pre-tiled, SW128-swizzled fp16 operands.
// A-side: single fp16 (rounded). B-side: hi + lo (hi+lo ~= fp32).
// Tile (rowTile, kTile) of 128x64 halfs = 16 KB contiguous; SW128 inside.
__device__ __half g_xh [(size_t)NNP * KP1];
__device__ __half g_W1h[(size_t)HF * KP1];
__device__ __half g_W1l[(size_t)HF * KP1];
__device__ __half g_A2h[(size_t)NNP * HF];
__device__ __half g_W2h[(size_t)HF * HF];
__device__ __half g_W2l[(size_t)HF * HF];
__device__ __half g_XCh[(size_t)MMP * HF];
__device__ __half g_WCh[(size_t)2048 * HF];
__device__ __half g_WCl[(size_t)2048 * HF];

// ---------------- low-level helpers ------------------------------------------
__device__ __forceinline__ uint32_t smem_u32(const void* p) {
    uint32_t a;
    asm("{ .reg .u64 t; cvta.to.shared.u64 t, %1; cvt.u32.u64 %0, t; }"
        : "=r"(a) : "l"(p));
    return a;
}

__device__ __forceinline__ void bulkcp(uint32_t dst, const void* src,
                                       uint32_t bytes, uint32_t mbar) {
    asm volatile(
        "cp.async.bulk.shared::cluster.global.mbarrier::complete_tx::bytes "
        "[%0], [%1], %2, [%3];"
        :: "r"(dst), "l"(src), "r"(bytes), "r"(mbar) : "memory");
}

#define MBAR_INIT(addr, cnt) \
    asm volatile("mbarrier.init.shared.b64 [%0], %1;" \
                 :: "r"((uint32_t)(addr)), "r"((uint32_t)(cnt)) : "memory")
#define MBAR_EXPECT(addr, tx) \
    asm volatile("mbarrier.arrive.expect_tx.shared.b64 _, [%0], %1;" \
                 :: "r"((uint32_t)(addr)), "r"((uint32_t)(tx)) : "memory")
#define MBAR_WAIT(addr, parity) do {                                           \
    uint32_t _m = (uint32_t)(addr); uint32_t _p = (uint32_t)(parity);          \
    uint32_t _d;                                                               \
    asm volatile("{\n\t.reg .pred p;\n\t"                                      \
        "mbarrier.try_wait.parity.acquire.cta.shared::cta.b64 p, [%1], %2;\n\t"\
        "selp.b32 %0, 1, 0, p;\n\t}" : "=r"(_d) : "r"(_m), "r"(_p) : "memory");\
    if (!_d) {                                                                 \
        asm volatile("{\n\t.reg .pred P1;\n\t"                                 \
            "WL_%=:\n\t"                                                       \
            "mbarrier.try_wait.parity.acquire.cta.shared::cta.b64 P1, [%0], %1, 0x989680;\n\t" \
            "@P1 bra.uni WD_%=;\n\t"                                           \
            "bra.uni WL_%=;\n\t"                                               \
            "WD_%=:\n\t}" :: "r"(_m), "r"(_p) : "memory");                     \
    }                                                                          \
} while (0)

__device__ __forceinline__ void ldsm4(uint32_t* r, uint32_t addr) {
    asm volatile("ldmatrix.sync.aligned.m8n8.x4.shared.b16 {%0,%1,%2,%3}, [%4];"
                 : "=r"(r[0]), "=r"(r[1]), "=r"(r[2]), "=r"(r[3]) : "r"(addr));
}

__device__ __forceinline__ void mma16816(float* d, const uint32_t* a,
                                         uint32_t b0, uint32_t b1) {
    asm volatile(
        "mma.sync.aligned.m16n8k16.row.col.f32.f16.f16.f32 "
        "{%0,%1,%2,%3}, {%4,%5,%6,%7}, {%8,%9}, {%0,%1,%2,%3};"
        : "+f"(d[0]), "+f"(d[1]), "+f"(d[2]), "+f"(d[3])
        : "r"(a[0]), "r"(a[1]), "r"(a[2]), "r"(a[3]), "r"(b0), "r"(b1));
}

// Element offset inside the tiled+swizzled operand layout.
__device__ __forceinline__ size_t tileoff(int row, int k, int KT) {
    size_t base = ((size_t)((row >> 7) * KT + (k >> 6))) << 13;
    uint32_t boff = ((uint32_t)(row & 127) << 7) | ((uint32_t)(k & 63) << 1);
    uint32_t sw = boff ^ ((boff >> 3) & 0x70);
    return base + (sw >> 1);
}

__device__ __forceinline__ uint32_t swz(uint32_t boff) {
    return boff ^ ((boff >> 3) & 0x70);
}

// ---------------- bulk-loaded tensor-core GEMM (fp16 2-term) -----------------
// C = Ah[M,K] @ (Bh+Bl)[N,K]^T.  Stage = {A, Bhi, Blo} 16 KB tiles.
// MODE 0: C[r*Ncols+c] = acc + bias[c]; also accumulates per-column
//         sum / sumsq of the biased output into statSum/statSq (BN stats).
// MODE 1: layer-3 epilogue: +PB/PA[label] table, 2M-row output layout.
#define TILE16K 16384
#define STG48K  49152
#define NSTAGE  4
#define SMEM_GG (NSTAGE * STG48K + 32)

template <int MODE>
__global__ void __launch_bounds__(256)
k_bulkmma(const __half* __restrict__ Ah_, const __half* __restrict__ Bh_,
          const __half* __restrict__ Bl_,
          int Mrows, int Ncols, int KT,
          const float* __restrict__ bias, float* __restrict__ Cmat,
          float* __restrict__ statSum, float* __restrict__ statSq,
          const int* __restrict__ labels, const float* __restrict__ PA,
          const float* __restrict__ PB, float* __restrict__ out) {
    extern __shared__ unsigned char smem[];
    const uint32_t sb = smem_u32(smem);
    const uint32_t mb = sb + NSTAGE * STG48K;   // mbarriers, 8 B apart
    const int tx = threadIdx.x;
    const int lane = tx & 31, wid = tx >> 5;
    const int warpM = wid & 3;           // 4 warps over M (32 rows each)
    const int warpN = wid >> 2;          // 2 warps over N (64 cols each)
    const int rowBase = blockIdx.y * 128;
    const int colBase = blockIdx.x * 128;

    if (tx == 0) {
#pragma unroll
        for (int s = 0; s < NSTAGE; s++) MBAR_INIT(mb + 8 * s, 1);
    }
    __syncthreads();

    const size_t aBase = ((size_t)blockIdx.y * KT) << 13;
    const size_t bBase = ((size_t)blockIdx.x * KT) << 13;

    if (tx == 0) {
        const int pre = (KT < NSTAGE) ? KT : NSTAGE;
        for (int s = 0; s < pre; s++) {
            const size_t off = aBase + ((size_t)s << 13);
            const size_t bof = bBase + ((size_t)s << 13);
            MBAR_EXPECT(mb + 8 * s, STG48K);
            uint32_t d = sb + (uint32_t)s * STG48K;
            bulkcp(d + 0 * TILE16K, Ah_ + off, TILE16K, mb + 8 * s);
            bulkcp(d + 1 * TILE16K, Bh_ + bof, TILE16K, mb + 8 * s);
            bulkcp(d + 2 * TILE16K, Bl_ + bof, TILE16K, mb + 8 * s);
        }
    }

    float acc[2][8][4];
#pragma unroll
    for (int i = 0; i < 2; i++)
#pragma unroll
        for (int j = 0; j < 8; j++)
#pragma unroll
            for (int q = 0; q < 4; q++) acc[i][j][q] = 0.f;

    int ph[NSTAGE] = {0, 0, 0, 0};
    for (int c = 0; c < KT; c++) {
        const int s = c % NSTAGE;
        MBAR_WAIT(mb + 8 * s, ph[s]);
        ph[s] ^= 1;
        const uint32_t stg = sb + (uint32_t)s * STG48K;
#pragma unroll
        for (int ks = 0; ks < 4; ks++) {
            const int k0 = ks * 16;
            uint32_t ah[2][4], bh[4][4], bl[4][4];
#pragma unroll
            for (int mf = 0; mf < 2; mf++) {
                uint32_t boff = ((uint32_t)(warpM * 32 + mf * 16 + (lane & 15)) << 7) |
                                ((uint32_t)(k0 + (lane >> 4) * 8) << 1);
                ldsm4(ah[mf], stg + 0 * TILE16K + swz(boff));
            }
            {
                const int grp = lane >> 3, rin = lane & 7;
#pragma unroll
                for (int p = 0; p < 4; p++) {
                    uint32_t boff = ((uint32_t)(warpN * 64 + p * 16 + (grp >> 1) * 8 + rin) << 7) |
                                    ((uint32_t)(k0 + (grp & 1) * 8) << 1);
                    uint32_t off = swz(boff);
                    ldsm4(bh[p], stg + 1 * TILE16K + off);
                    ldsm4(bl[p], stg + 2 * TILE16K + off);
                }
            }
            // term 1: A * Bhi
#pragma unroll
            for (int p = 0; p < 4; p++)
#pragma unroll
                for (int mf = 0; mf < 2; mf++) {
                    mma16816(acc[mf][2 * p + 0], ah[mf], bh[p][0], bh[p][1]);
                    mma16816(acc[mf][2 * p + 1], ah[mf], bh[p][2], bh[p][3]);
                }
            // term 2: A * Blo
#pragma unroll
            for (int p = 0; p < 4; p++)
#pragma unroll
                for (int mf = 0; mf < 2; mf++) {
                    mma16816(acc[mf][2 * p + 0], ah[mf], bl[p][0], bl[p][1]);
                    mma16816(acc[mf][2 * p + 1], ah[mf], bl[p][2], bl[p][3]);
                }
        }
        __syncthreads();
        if (c + NSTAGE < KT && tx == 0) {
            const int cn = c + NSTAGE;
            const size_t off = aBase + ((size_t)cn << 13);
            const size_t bof = bBase + ((size_t)cn << 13);
            MBAR_EXPECT(mb + 8 * s, STG48K);
            uint32_t d = sb + (uint32_t)s * STG48K;
            bulkcp(d + 0 * TILE16K, Ah_ + off, TILE16K, mb + 8 * s);
            bulkcp(d + 1 * TILE16K, Bh_ + bof, TILE16K, mb + 8 * s);
            bulkcp(d + 2 * TILE16K, Bl_ + bof, TILE16K, mb + 8 * s);
        }
    }

    // ---------------- epilogue ----------------
    if (MODE == 0) {
        float colS[16], colQ[16];
#pragma unroll
        for (int i = 0; i < 16; i++) { colS[i] = 0.f; colQ[i] = 0.f; }
#pragma unroll
        for (int mf = 0; mf < 2; mf++) {
#pragma unroll
            for (int half = 0; half < 2; half++) {
                const int r = rowBase + warpM * 32 + mf * 16 + (lane >> 2) + half * 8;
                if (r >= Mrows) continue;
                float* cp = Cmat + (size_t)r * Ncols;
#pragma unroll
                for (int nf = 0; nf < 8; nf++) {
                    const int cc = colBase + warpN * 64 + nf * 8 + (lane & 3) * 2;
                    float2 b = *(const float2*)(bias + cc);
                    float v0 = acc[mf][nf][half * 2 + 0] + b.x;
                    float v1 = acc[mf][nf][half * 2 + 1] + b.y;
                    *(float2*)(cp + cc) = make_float2(v0, v1);
                    colS[nf * 2 + 0] += v0;
                    colQ[nf * 2 + 0] = fmaf(v0, v0, colQ[nf * 2 + 0]);
                    colS[nf * 2 + 1] += v1;
                    colQ[nf * 2 + 1] = fmaf(v1, v1, colQ[nf * 2 + 1]);
                }
            }
        }
        // reduce per-column stats in SMEM (tiles no longer needed)
        float* ssum = (float*)smem;
        float* ssq  = ssum + 128;
        if (tx < 128) { ssum[tx] = 0.f; ssq[tx] = 0.f; }
        __syncthreads();
        const int cbl = warpN * 64 + (lane & 3) * 2;
#pragma unroll
        for (int nf = 0; nf < 8; nf++) {
#pragma unroll
            for (int sc = 0; sc < 2; sc++) {
                const int ci = cbl + nf * 8 + sc;
                atomicAdd(&ssum[ci], colS[nf * 2 + sc]);
                atomicAdd(&ssq[ci],  colQ[nf * 2 + sc]);
            }
        }
        __syncthreads();
        if (tx < 128) {
            atomicAdd(&statSum[colBase + tx], ssum[tx]);
            atomicAdd(&statSq[colBase + tx],  ssq[tx]);
        }
    } else {
#pragma unroll
        for (int mf = 0; mf < 2; mf++) {
#pragma unroll
            for (int half = 0; half < 2; half++) {
                const int r = rowBase + warpM * 32 + mf * 16 + (lane >> 2) + half * 8;
                if (r >= Mrows) continue;
                const bool hB = colBase >= 1024;   // Wcat rows >=1024 = WfcB half
                const int lab = labels[r];
                const float* P = hB ? PA : PB;
                const float* pl = P + (size_t)lab * O2;
                float* op = out + ((size_t)r + (hB ? (size_t)MM : 0)) * O2;
                const int cB = (colBase & 1023) + warpN * 64;
#pragma unroll
                for (int nf = 0; nf < 8; nf++) {
                    const int col = cB + nf * 8 + (lane & 3) * 2;
                    float2 p = *(const float2*)(pl + col);
                    float2 v;
                    v.x = acc[mf][nf][half * 2 + 0] + p.x;
                    v.y = acc[mf][nf][half * 2 + 1] + p.y;
                    *(float2*)(op + col) = v;
                }
            }
        }
    }
}

// ---------------- split kernels: fp32 -> tiled swizzled fp16 ----------------
// A-side: single rounded fp16. One thread = 8 consecutive k (one 16B group).
__global__ void k_split_a(const float* __restrict__ src,
                          __half* __restrict__ dst,
                          int rowsSrc, int colsSrc, int K8, int KT,
                          long long total) {
    long long idx = blockIdx.x * (long long)blockDim.x + threadIdx.x;
    if (idx >= total) return;
    int row = (int)(idx / K8);
    int k   = (int)(idx % K8) * 8;
    __half h8[8];
#pragma unroll
    for (int j = 0; j < 8; j++) {
        float v = 0.f;
        if (row < rowsSrc && k + j < colsSrc)
            v = src[(size_t)row * colsSrc + k + j];
        h8[j] = __float2half(v);
    }
    *(uint4*)(dst + tileoff(row, k, KT)) = *(uint4*)h8;
}

// B-side: hi + lo fp16.
__global__ void k_split_b(const float* __restrict__ src,
                          __half* __restrict__ hi, __half* __restrict__ lo,
                          int rowsSrc, int colsSrc, int K8, int KT,
                          long long total) {
    long long idx = blockIdx.x * (long long)blockDim.x + threadIdx.x;
    if (idx >= total) return;
    int row = (int)(idx / K8);
    int k   = (int)(idx % K8) * 8;
    __half h8[8], l8[8];
#pragma unroll
    for (int j = 0; j < 8; j++) {
        float v = 0.f;
        if (row < rowsSrc && k + j < colsSrc)
            v = src[(size_t)row * colsSrc + k + j];
        __half h = __float2half(v);
        h8[j] = h;
        l8[j] = __float2half(v - __half2float(h));
    }
    size_t off = tileoff(row, k, KT);
    *(uint4*)(hi + off) = *(uint4*)h8;
    *(uint4*)(lo + off) = *(uint4*)l8;
}

__global__ void k_split_aff_a(const float* __restrict__ src,
                              const float* __restrict__ aa, const float* __restrict__ cc,
                              __half* __restrict__ dst,
                              int rowsSrc, long long total) {
    long long idx = blockIdx.x * (long long)blockDim.x + threadIdx.x;
    if (idx >= total) return;
    int row = (int)(idx / (HF / 8));
    int k   = (int)(idx % (HF / 8)) * 8;
    __half h8[8];
#pragma unroll
    for (int j = 0; j < 8; j++) {
        float v = 0.f;
        if (row < rowsSrc)
            v = fmaxf(fmaf(aa[k + j], src[(size_t)row * HF + k + j], cc[k + j]), 0.f);
        h8[j] = __float2half(v);
    }
    *(uint4*)(dst + tileoff(row, k, HF / 64)) = *(uint4*)h8;
}

// Wcat[2048,256]: rows 0..1023 = Wfc[:, :256]; rows 1024..2047 = Wfc[:, 256:]
__global__ void k_split_wcat(const float* __restrict__ Wfc,
                             __half* __restrict__ hi, __half* __restrict__ lo) {
    int idx = blockIdx.x * blockDim.x + threadIdx.x;
    if (idx >= 2048 * (HF / 8)) return;
    int o = idx / (HF / 8);
    int k = (idx % (HF / 8)) * 8;
    const float* w = (o < 1024) ? (Wfc + (size_t)o * (2 * HF))
                                : (Wfc + (size_t)(o - 1024) * (2 * HF) + HF);
    __half h8[8], l8[8];
#pragma unroll
    for (int j = 0; j < 8; j++) {
        float v = w[k + j];
        __half h = __float2half(v);
        h8[j] = h;
        l8[j] = __float2half(v - __half2float(h));
    }
    size_t off = tileoff(o, k, HF / 64);
    *(uint4*)(hi + off) = *(uint4*)h8;
    *(uint4*)(lo + off) = *(uint4*)l8;
}

// ---------------- stats / labels / segment mean ------------------------------
__global__ void k_zero(float* s1, float* q1, float* s2, float* q2,
                       float* cfs, int* cnt) {
    int t = blockIdx.x * blockDim.x + threadIdx.x;
    if (t < HF) { s1[t] = 0.f; q1[t] = 0.f; s2[t] = 0.f; q2[t] = 0.f; }
    if (t < KC) cnt[t] = 0;
    if (t < KC * HF) cfs[t] = 0.f;
}

__global__ void k_finalize(const float* __restrict__ sum, const float* __restrict__ sq,
                           const float* __restrict__ gam, const float* __restrict__ bet,
                           float* __restrict__ a, float* __restrict__ c) {
    int t = threadIdx.x;
    const float invN = 1.0f / (float)NN;
    float mean = sum[t] * invN;
    float var  = sq[t] * invN - mean * mean;
    float inv  = rsqrtf(var + EPSV);
    float aa   = gam[t] * inv;
    a[t] = aa;
    c[t] = bet[t] - mean * aa;
}

__global__ void k_labels(const float* __restrict__ cid,
                         int* __restrict__ labels, int* __restrict__ cnt) {
    int m = blockIdx.x * blockDim.x + threadIdx.x;
    if (m >= MM) return;
    const float* row = cid + (size_t)m * KC;
    int best = 0;
    float bv = row[0];
#pragma unroll
    for (int k = 1; k < KC; k++) {
        float v = row[k];
        if (v > bv) { bv = v; best = k; }
    }
    labels[m] = best;
    atomicAdd(&cnt[best], 1);
}

// XC = relu(a2*H2[ci[m]] + c2): fp32 copy (for cluster sums) + tiled fp16
__global__ void k_make_xc(const float* __restrict__ H2, const int* __restrict__ ci,
                          const float* __restrict__ a2, const float* __restrict__ c2,
                          float* __restrict__ XC, __half* __restrict__ dst) {
    int idx = blockIdx.x * blockDim.x + threadIdx.x;
    if (idx >= MMP * (HF / 8)) return;
    int m = idx / (HF / 8);
    int k = (idx % (HF / 8)) * 8;
    __half h8[8];
    float o8[8];
#pragma unroll
    for (int j = 0; j < 8; j++) o8[j] = 0.f;
    if (m < MM) {
        int r = ci[m];
        const float* hp = H2 + (size_t)r * HF + k;
#pragma unroll
        for (int j = 0; j < 8; j++)
            o8[j] = fmaxf(fmaf(a2[k + j], hp[j], c2[k + j]), 0.f);
        float4* xp = (float4*)(XC + (size_t)m * HF + k);
        xp[0] = make_float4(o8[0], o8[1], o8[2], o8[3]);
        xp[1] = make_float4(o8[4], o8[5], o8[6], o8[7]);
    }
#pragma unroll
    for (int j = 0; j < 8; j++) h8[j] = __float2half(o8[j]);
    *(uint4*)(dst + tileoff(m, k, HF / 64)) = *(uint4*)h8;
}

__global__ void k_cluster_accum(const float* __restrict__ XC,
                                const int* __restrict__ labels,
                                float* __restrict__ CFsum) {
    __shared__ float acc[KC * HF];
    int t = threadIdx.x;
    for (int i = t; i < KC * HF; i += blockDim.x) acc[i] = 0.f;
    __syncthreads();
    int per = (MM + gridDim.x - 1) / gridDim.x;
    int m0 = blockIdx.x * per;
    int m1 = min(MM, m0 + per);
    for (int m = m0; m < m1; m++) {
        int lab = labels[m];
        acc[lab * HF + t] += XC[(size_t)m * HF + t];
    }
    __syncthreads();
    for (int i = t; i < KC * HF; i += blockDim.x) atomicAdd(&CFsum[i], acc[i]);
}

__global__ void k_ptab(const float* __restrict__ Wfc, const float* __restrict__ bfc,
                       const float* __restrict__ CFsum, const int* __restrict__ cnt,
                       float* __restrict__ PA, float* __restrict__ PB) {
    __shared__ float cf[HF];
    int k = blockIdx.y;
    int t = threadIdx.x;
    float cnv = (float)cnt[k];
    cf[t] = CFsum[k * HF + t] / cnv;
    __syncthreads();
    int o = blockIdx.x * 256 + t;
    const float* w = Wfc + (size_t)o * (2 * HF);
    float sa = 0.f, sb = 0.f;
#pragma unroll 4
    for (int j = 0; j < HF; j++) {
        float c = cf[j];
        sa = fmaf(c, w[j], sa);
        sb = fmaf(c, w[HF + j], sb);
    }
    float bb = bfc[o];
    PA[k * O2 + o] = sa + bb;
    PB[k * O2 + o] = sb + bb;
}

// ---------------- host launcher ---------------------------------------------
extern "C" void kernel_launch(void* const* d_in, const int* in_sizes, int n_in,
                              void* d_out, int out_size) {
    const float* x    = (const float*)d_in[0];
    const float* cid  = (const float*)d_in[1];
    const int*   cidx = (const int*)  d_in[2];
    const float* W1   = (const float*)d_in[3];
    const float* b1   = (const float*)d_in[4];
    const float* g1   = (const float*)d_in[5];
    const float* be1  = (const float*)d_in[6];
    const float* W2   = (const float*)d_in[7];
    const float* b2   = (const float*)d_in[8];
    const float* g2   = (const float*)d_in[9];
    const float* be2  = (const float*)d_in[10];
    const float* Wfc  = (const float*)d_in[11];
    const float* bfc  = (const float*)d_in[12];
    float* out = (float*)d_out;

    static bool inited = false;
    static float *H1, *H2, *XC, *sum1, *sq1, *a1, *c1, *sum2, *sq2, *a2, *c2,
                 *CFs, *PA, *PB;
    static int *cnt, *labs;
    static __half *xh, *W1h, *W1l, *A2h, *W2h, *W2l, *XCh, *WCh, *WCl;
    if (!inited) {
        inited = true;
        cudaGetSymbolAddress((void**)&H1,   g_H1);
        cudaGetSymbolAddress((void**)&H2,   g_H2);
        cudaGetSymbolAddress((void**)&XC,   g_XC);
        cudaGetSymbolAddress((void**)&sum1, g_sum1);
        cudaGetSymbolAddress((void**)&sq1,  g_sq1);
        cudaGetSymbolAddress((void**)&a1,   g_a1);
        cudaGetSymbolAddress((void**)&c1,   g_c1);
        cudaGetSymbolAddress((void**)&sum2, g_sum2);
        cudaGetSymbolAddress((void**)&sq2,  g_sq2);
        cudaGetSymbolAddress((void**)&a2,   g_a2);
        cudaGetSymbolAddress((void**)&c2,   g_c2);
        cudaGetSymbolAddress((void**)&CFs,  g_CFsum);
        cudaGetSymbolAddress((void**)&PA,   g_PA);
        cudaGetSymbolAddress((void**)&PB,   g_PB);
        cudaGetSymbolAddress((void**)&cnt,  g_counts);
        cudaGetSymbolAddress((void**)&labs, g_labels);
        cudaGetSymbolAddress((void**)&xh,   g_xh);
        cudaGetSymbolAddress((void**)&W1h,  g_W1h);
        cudaGetSymbolAddress((void**)&W1l,  g_W1l);
        cudaGetSymbolAddress((void**)&A2h,  g_A2h);
        cudaGetSymbolAddress((void**)&W2h,  g_W2h);
        cudaGetSymbolAddress((void**)&W2l,  g_W2l);
        cudaGetSymbolAddress((void**)&XCh,  g_XCh);
        cudaGetSymbolAddress((void**)&WCh,  g_WCh);
        cudaGetSymbolAddress((void**)&WCl,  g_WCl);
        cudaFuncSetAttribute(k_bulkmma<0>,
                             cudaFuncAttributeMaxDynamicSharedMemorySize, SMEM_GG);
        cudaFuncSetAttribute(k_bulkmma<1>,
                             cudaFuncAttributeMaxDynamicSharedMemorySize, SMEM_GG);
    }

    // 0) zero accumulators
    k_zero<<<40, 256>>>(sum1, sq1, sum2, sq2, CFs, cnt);

    // weight splits (B-side: hi/lo)
    {
        long long t1 = (long long)HF * (KP1 / 8);
        k_split_b<<<cdiv_h((int)t1, 256), 256>>>(W1, W1h, W1l,
                                                 HF, D_IN, KP1 / 8, KP1 / 64, t1);
        long long t2 = (long long)HF * (HF / 8);
        k_split_b<<<cdiv_h((int)t2, 256), 256>>>(W2, W2h, W2l,
                                                 HF, HF, HF / 8, HF / 64, t2);
        k_split_wcat<<<cdiv_h(2048 * (HF / 8), 256), 256>>>(Wfc, WCh, WCl);
    }
    // x (A-side: single fp16, rows padded to NNP, K padded to 512)
    {
        long long t = (long long)NNP * (KP1 / 8);
        k_split_a<<<(int)((t + 255) / 256), 256>>>(x, xh,
                                                   NN, D_IN, KP1 / 8, KP1 / 64, t);
    }

    // 1) H1 = x @ W1^T + b1  (stats fused into epilogue)
    {
        dim3 grid(HF / 128, NNP / 128);
        k_bulkmma<0><<<grid, 256, SMEM_GG>>>(xh, W1h, W1l,
            NN, HF, KP1 / 64, b1, H1, sum1, sq1, nullptr, nullptr, nullptr, nullptr);
    }
    k_finalize<<<1, 256>>>(sum1, sq1, g1, be1, a1, c1);

    // 2) A2 = relu(a1*H1 + c1) -> fp16; H2 = A2 @ W2^T + b2 (stats fused)
    {
        long long t = (long long)NNP * (HF / 8);
        k_split_aff_a<<<(int)((t + 255) / 256), 256>>>(H1, a1, c1, A2h, NN, t);
        dim3 grid(HF / 128, NNP / 128);
        k_bulkmma<0><<<grid, 256, SMEM_GG>>>(A2h, W2h, W2l,
            NN, HF, HF / 64, b2, H2, sum2, sq2, nullptr, nullptr, nullptr, nullptr);
    }
    k_finalize<<<1, 256>>>(sum2, sq2, g2, be2, a2, c2);

    // 3) labels + counts
    k_labels<<<cdiv_h(MM, 256), 256>>>(cid, labs, cnt);

    // 4) XC = relu(a2 * H2[cidx] + c2): fp32 + fused fp16 tiling
    k_make_xc<<<cdiv_h(MMP * (HF / 8), 256), 256>>>(H2, cidx, a2, c2, XC, XCh);

    // 5) cluster feature sums
    k_cluster_accum<<<256, 256>>>(XC, labs, CFs);

    // 6) PA/PB tables
    {
        dim3 grid(O2 / 256, KC);
        k_ptab<<<grid, 256>>>(Wfc, bfc, CFs, cnt, PA, PB);
    }

    // 7) final GEMM: Y = XC @ Wcat^T, epilogue adds PB/PA and scatters rows
    {
        dim3 grid(2048 / 128, MMP / 128);
        k_bulkmma<1><<<grid, 256, SMEM_GG>>>(XCh, WCh, WCl,
            MM, 2048, HF / 64, nullptr, nullptr, nullptr, nullptr,
            labs, PA, PB, out);
    }
}

// round 11
// speedup vs baseline: 1.3469x; 1.3469x over previous
#include <cuda_runtime.h>
#include <cuda_fp16.h>
#include <cstdint>

// ---------------- problem constants ----------------------------------------
#define NN   100000   // batch rows
#define NNP  100096   // padded to 128
#define D_IN 500      // input features
#define KP1  512      // D_IN padded to MMA K granularity
#define HF   256      // hidden
#define MM   50000    // cluster rows
#define MMP  50048    // padded to 128
#define KC   40       // clusters
#define O2   1024     // OUT*OUT
#define EPSV 1e-5f

static inline int cdiv_h(int a, int b) { return (a + b - 1) / b; }

// ---------------- device scratch --------------------------------------------
__device__ float g_H1[(size_t)NN * HF];
__device__ float g_H2[(size_t)NN * HF];
__device__ float g_XC[(size_t)MM * HF];
__device__ float g_sum1[HF], g_sq1[HF], g_a1[HF], g_c1[HF];
__device__ float g_sum2[HF], g_sq2[HF], g_a2[HF], g_c2[HF];
__device__ float g_CFsum[KC * HF];
__device__ int   g_counts[KC];
__device__ int   g_labels[MM];
__device__ float g_PA[KC * O2];
__device__ float g_PB[KC * O2];

// Pre-tiled, SW128-swizzled fp16 operands.
// A-side: single fp16 (rounded). B-side: hi + lo (hi+lo ~= fp32).
// Tile (rowTile, kTile) of 128x64 halfs = 16 KB contiguous; SW128 inside.
__device__ __half g_xh [(size_t)NNP * KP1];
__device__ __half g_W1h[(size_t)HF * KP1];
__device__ __half g_W1l[(size_t)HF * KP1];
__device__ __half g_A2h[(size_t)NNP * HF];
__device__ __half g_W2h[(size_t)HF * HF];
__device__ __half g_W2l[(size_t)HF * HF];
__device__ __half g_XCh[(size_t)MMP * HF];
__device__ __half g_WCh[(size_t)2048 * HF];
__device__ __half g_WCl[(size_t)2048 * HF];

// ---------------- low-level helpers ------------------------------------------
__device__ __forceinline__ uint32_t smem_u32(const void* p) {
    uint32_t a;
    asm("{ .reg .u64 t; cvta.to.shared.u64 t, %1; cvt.u32.u64 %0, t; }"
        : "=r"(a) : "l"(p));
    return a;
}

__device__ __forceinline__ void bulkcp(uint32_t dst, const void* src,
                                       uint32_t bytes, uint32_t mbar) {
    asm volatile(
        "cp.async.bulk.shared::cluster.global.mbarrier::complete_tx::bytes "
        "[%0], [%1], %2, [%3];"
        :: "r"(dst), "l"(src), "r"(bytes), "r"(mbar) : "memory");
}

#define MBAR_INIT(addr, cnt) \
    asm volatile("mbarrier.init.shared.b64 [%0], %1;" \
                 :: "r"((uint32_t)(addr)), "r"((uint32_t)(cnt)) : "memory")
#define MBAR_EXPECT(addr, tx) \
    asm volatile("mbarrier.arrive.expect_tx.shared.b64 _, [%0], %1;" \
                 :: "r"((uint32_t)(addr)), "r"((uint32_t)(tx)) : "memory")
#define MBAR_WAIT(addr, parity) do {                                           \
    uint32_t _m = (uint32_t)(addr); uint32_t _p = (uint32_t)(parity);          \
    uint32_t _d;                                                               \
    asm volatile("{\n\t.reg .pred p;\n\t"                                      \
        "mbarrier.try_wait.parity.acquire.cta.shared::cta.b64 p, [%1], %2;\n\t"\
        "selp.b32 %0, 1, 0, p;\n\t}" : "=r"(_d) : "r"(_m), "r"(_p) : "memory");\
    if (!_d) {                                                                 \
        asm volatile("{\n\t.reg .pred P1;\n\t"                                 \
            "WL_%=:\n\t"                                                       \
            "mbarrier.try_wait.parity.acquire.cta.shared::cta.b64 P1, [%0], %1, 0x989680;\n\t" \
            "@P1 bra.uni WD_%=;\n\t"                                           \
            "bra.uni WL_%=;\n\t"                                               \
            "WD_%=:\n\t}" :: "r"(_m), "r"(_p) : "memory");                     \
    }                                                                          \
} while (0)

__device__ __forceinline__ void ldsm4(uint32_t* r, uint32_t addr) {
    asm volatile("ldmatrix.sync.aligned.m8n8.x4.shared.b16 {%0,%1,%2,%3}, [%4];"
                 : "=r"(r[0]), "=r"(r[1]), "=r"(r[2]), "=r"(r[3]) : "r"(addr));
}

__device__ __forceinline__ void mma16816(float* d, const uint32_t* a,
                                         uint32_t b0, uint32_t b1) {
    asm volatile(
        "mma.sync.aligned.m16n8k16.row.col.f32.f16.f16.f32 "
        "{%0,%1,%2,%3}, {%4,%5,%6,%7}, {%8,%9}, {%0,%1,%2,%3};"
        : "+f"(d[0]), "+f"(d[1]), "+f"(d[2]), "+f"(d[3])
        : "r"(a[0]), "r"(a[1]), "r"(a[2]), "r"(a[3]), "r"(b0), "r"(b1));
}

// Element offset inside the tiled+swizzled operand layout.
__device__ __forceinline__ size_t tileoff(int row, int k, int KT) {
    size_t base = ((size_t)((row >> 7) * KT + (k >> 6))) << 13;
    uint32_t boff = ((uint32_t)(row & 127) << 7) | ((uint32_t)(k & 63) << 1);
    uint32_t sw = boff ^ ((boff >> 3) & 0x70);
    return base + (sw >> 1);
}

__device__ __forceinline__ uint32_t swz(uint32_t boff) {
    return boff ^ ((boff >> 3) & 0x70);
}

// ---------------- bulk-loaded tensor-core GEMM (fp16 2-term) -----------------
// C = Ah[M,K] @ (Bh+Bl)[N,K]^T.  Stage = {A, Bhi, Blo} 16 KB tiles.
// MODE 0: C[r*Ncols+c] = acc + bias[c]
// MODE 1: layer-3 epilogue: +PB/PA[label] table, 2M-row output layout.
#define TILE16K 16384
#define STG48K  49152
#define NSTAGE  4
#define SMEM_GG (NSTAGE * STG48K + 32)

template <int MODE>
__global__ void __launch_bounds__(256)
k_bulkmma(const __half* __restrict__ Ah_, const __half* __restrict__ Bh_,
          const __half* __restrict__ Bl_,
          int Mrows, int Ncols, int KT,
          const float* __restrict__ bias, float* __restrict__ Cmat,
          const int* __restrict__ labels, const float* __restrict__ PA,
          const float* __restrict__ PB, float* __restrict__ out) {
    extern __shared__ unsigned char smem[];
    const uint32_t sb = smem_u32(smem);
    const uint32_t mb = sb + NSTAGE * STG48K;   // mbarriers, 8 B apart
    const int tx = threadIdx.x;
    const int lane = tx & 31, wid = tx >> 5;
    const int warpM = wid & 3;           // 4 warps over M (32 rows each)
    const int warpN = wid >> 2;          // 2 warps over N (64 cols each)
    const int rowBase = blockIdx.y * 128;
    const int colBase = blockIdx.x * 128;

    if (tx == 0) {
#pragma unroll
        for (int s = 0; s < NSTAGE; s++) MBAR_INIT(mb + 8 * s, 1);
    }
    __syncthreads();

    const size_t aBase = ((size_t)blockIdx.y * KT) << 13;
    const size_t bBase = ((size_t)blockIdx.x * KT) << 13;

    if (tx == 0) {
        const int pre = (KT < NSTAGE) ? KT : NSTAGE;
        for (int s = 0; s < pre; s++) {
            const size_t off = aBase + ((size_t)s << 13);
            const size_t bof = bBase + ((size_t)s << 13);
            MBAR_EXPECT(mb + 8 * s, STG48K);
            uint32_t d = sb + (uint32_t)s * STG48K;
            bulkcp(d + 0 * TILE16K, Ah_ + off, TILE16K, mb + 8 * s);
            bulkcp(d + 1 * TILE16K, Bh_ + bof, TILE16K, mb + 8 * s);
            bulkcp(d + 2 * TILE16K, Bl_ + bof, TILE16K, mb + 8 * s);
        }
    }

    float acc[2][8][4];
#pragma unroll
    for (int i = 0; i < 2; i++)
#pragma unroll
        for (int j = 0; j < 8; j++)
#pragma unroll
            for (int q = 0; q < 4; q++) acc[i][j][q] = 0.f;

    int ph[NSTAGE] = {0, 0, 0, 0};
    for (int c = 0; c < KT; c++) {
        const int s = c % NSTAGE;
        MBAR_WAIT(mb + 8 * s, ph[s]);
        ph[s] ^= 1;
        const uint32_t stg = sb + (uint32_t)s * STG48K;
#pragma unroll
        for (int ks = 0; ks < 4; ks++) {
            const int k0 = ks * 16;
            uint32_t ah[2][4], bh[4][4], bl[4][4];
#pragma unroll
            for (int mf = 0; mf < 2; mf++) {
                uint32_t boff = ((uint32_t)(warpM * 32 + mf * 16 + (lane & 15)) << 7) |
                                ((uint32_t)(k0 + (lane >> 4) * 8) << 1);
                ldsm4(ah[mf], stg + 0 * TILE16K + swz(boff));
            }
            {
                const int grp = lane >> 3, rin = lane & 7;
#pragma unroll
                for (int p = 0; p < 4; p++) {
                    uint32_t boff = ((uint32_t)(warpN * 64 + p * 16 + (grp >> 1) * 8 + rin) << 7) |
                                    ((uint32_t)(k0 + (grp & 1) * 8) << 1);
                    uint32_t off = swz(boff);
                    ldsm4(bh[p], stg + 1 * TILE16K + off);
                    ldsm4(bl[p], stg + 2 * TILE16K + off);
                }
            }
            // term 1: A * Bhi
#pragma unroll
            for (int p = 0; p < 4; p++)
#pragma unroll
                for (int mf = 0; mf < 2; mf++) {
                    mma16816(acc[mf][2 * p + 0], ah[mf], bh[p][0], bh[p][1]);
                    mma16816(acc[mf][2 * p + 1], ah[mf], bh[p][2], bh[p][3]);
                }
            // term 2: A * Blo
#pragma unroll
            for (int p = 0; p < 4; p++)
#pragma unroll
                for (int mf = 0; mf < 2; mf++) {
                    mma16816(acc[mf][2 * p + 0], ah[mf], bl[p][0], bl[p][1]);
                    mma16816(acc[mf][2 * p + 1], ah[mf], bl[p][2], bl[p][3]);
                }
        }
        __syncthreads();
        if (c + NSTAGE < KT && tx == 0) {
            const int cn = c + NSTAGE;
            const size_t off = aBase + ((size_t)cn << 13);
            const size_t bof = bBase + ((size_t)cn << 13);
            MBAR_EXPECT(mb + 8 * s, STG48K);
            uint32_t d = sb + (uint32_t)s * STG48K;
            bulkcp(d + 0 * TILE16K, Ah_ + off, TILE16K, mb + 8 * s);
            bulkcp(d + 1 * TILE16K, Bh_ + bof, TILE16K, mb + 8 * s);
            bulkcp(d + 2 * TILE16K, Bl_ + bof, TILE16K, mb + 8 * s);
        }
    }

    // ---------------- epilogue (plain, no fused stats) ----------------------
#pragma unroll
    for (int mf = 0; mf < 2; mf++) {
#pragma unroll
        for (int half = 0; half < 2; half++) {
            const int r = rowBase + warpM * 32 + mf * 16 + (lane >> 2) + half * 8;
            if (r >= Mrows) continue;
            if (MODE == 0) {
                float* cp = Cmat + (size_t)r * Ncols;
#pragma unroll
                for (int nf = 0; nf < 8; nf++) {
                    const int cc = colBase + warpN * 64 + nf * 8 + (lane & 3) * 2;
                    float2 b = *(const float2*)(bias + cc);
                    float2 v;
                    v.x = acc[mf][nf][half * 2 + 0] + b.x;
                    v.y = acc[mf][nf][half * 2 + 1] + b.y;
                    *(float2*)(cp + cc) = v;
                }
            } else {
                const bool hB = colBase >= 1024;   // Wcat rows >=1024 = WfcB half
                const int lab = labels[r];
                const float* P = hB ? PA : PB;
                const float* pl = P + (size_t)lab * O2;
                float* op = out + ((size_t)r + (hB ? (size_t)MM : 0)) * O2;
                const int cB = (colBase & 1023) + warpN * 64;
#pragma unroll
                for (int nf = 0; nf < 8; nf++) {
                    const int col = cB + nf * 8 + (lane & 3) * 2;
                    float2 p = *(const float2*)(pl + col);
                    float2 v;
                    v.x = acc[mf][nf][half * 2 + 0] + p.x;
                    v.y = acc[mf][nf][half * 2 + 1] + p.y;
                    *(float2*)(op + col) = v;
                }
            }
        }
    }
}

// ---------------- split kernels: fp32 -> tiled swizzled fp16 ----------------
__global__ void k_split_a(const float* __restrict__ src,
                          __half* __restrict__ dst,
                          int rowsSrc, int colsSrc, int K8, int KT,
                          long long total) {
    long long idx = blockIdx.x * (long long)blockDim.x + threadIdx.x;
    if (idx >= total) return;
    int row = (int)(idx / K8);
    int k   = (int)(idx % K8) * 8;
    __half h8[8];
#pragma unroll
    for (int j = 0; j < 8; j++) {
        float v = 0.f;
        if (row < rowsSrc && k + j < colsSrc)
            v = src[(size_t)row * colsSrc + k + j];
        h8[j] = __float2half(v);
    }
    *(uint4*)(dst + tileoff(row, k, KT)) = *(uint4*)h8;
}

__global__ void k_split_b(const float* __restrict__ src,
                          __half* __restrict__ hi, __half* __restrict__ lo,
                          int rowsSrc, int colsSrc, int K8, int KT,
                          long long total) {
    long long idx = blockIdx.x * (long long)blockDim.x + threadIdx.x;
    if (idx >= total) return;
    int row = (int)(idx / K8);
    int k   = (int)(idx % K8) * 8;
    __half h8[8], l8[8];
#pragma unroll
    for (int j = 0; j < 8; j++) {
        float v = 0.f;
        if (row < rowsSrc && k + j < colsSrc)
            v = src[(size_t)row * colsSrc + k + j];
        __half h = __float2half(v);
        h8[j] = h;
        l8[j] = __float2half(v - __half2float(h));
    }
    size_t off = tileoff(row, k, KT);
    *(uint4*)(hi + off) = *(uint4*)h8;
    *(uint4*)(lo + off) = *(uint4*)l8;
}

__global__ void k_split_aff_a(const float* __restrict__ src,
                              const float* __restrict__ aa, const float* __restrict__ cc,
                              __half* __restrict__ dst,
                              int rowsSrc, long long total) {
    long long idx = blockIdx.x * (long long)blockDim.x + threadIdx.x;
    if (idx >= total) return;
    int row = (int)(idx / (HF / 8));
    int k   = (int)(idx % (HF / 8)) * 8;
    __half h8[8];
#pragma unroll
    for (int j = 0; j < 8; j++) {
        float v = 0.f;
        if (row < rowsSrc)
            v = fmaxf(fmaf(aa[k + j], src[(size_t)row * HF + k + j], cc[k + j]), 0.f);
        h8[j] = __float2half(v);
    }
    *(uint4*)(dst + tileoff(row, k, HF / 64)) = *(uint4*)h8;
}

// Wcat[2048,256]: rows 0..1023 = Wfc[:, :256]; rows 1024..2047 = Wfc[:, 256:]
__global__ void k_split_wcat(const float* __restrict__ Wfc,
                             __half* __restrict__ hi, __half* __restrict__ lo) {
    int idx = blockIdx.x * blockDim.x + threadIdx.x;
    if (idx >= 2048 * (HF / 8)) return;
    int o = idx / (HF / 8);
    int k = (idx % (HF / 8)) * 8;
    const float* w = (o < 1024) ? (Wfc + (size_t)o * (2 * HF))
                                : (Wfc + (size_t)(o - 1024) * (2 * HF) + HF);
    __half h8[8], l8[8];
#pragma unroll
    for (int j = 0; j < 8; j++) {
        float v = w[k + j];
        __half h = __float2half(v);
        h8[j] = h;
        l8[j] = __float2half(v - __half2float(h));
    }
    size_t off = tileoff(o, k, HF / 64);
    *(uint4*)(hi + off) = *(uint4*)h8;
    *(uint4*)(lo + off) = *(uint4*)l8;
}

// ---------------- stats / labels / segment mean ------------------------------
__global__ void k_zero(float* s1, float* q1, float* s2, float* q2,
                       float* cfs, int* cnt) {
    int t = blockIdx.x * blockDim.x + threadIdx.x;
    if (t < HF) { s1[t] = 0.f; q1[t] = 0.f; s2[t] = 0.f; q2[t] = 0.f; }
    if (t < KC) cnt[t] = 0;
    if (t < KC * HF) cfs[t] = 0.f;
}

__global__ void k_colstats(const float* __restrict__ H,
                           float* __restrict__ sum, float* __restrict__ sq) {
    int t = threadIdx.x;
    int per = (NN + gridDim.x - 1) / gridDim.x;
    int r0 = blockIdx.x * per;
    int r1 = min(NN, r0 + per);
    float s = 0.f, q = 0.f;
    for (int r = r0; r < r1; r++) {
        float v = H[(size_t)r * HF + t];
        s += v;
        q = fmaf(v, v, q);
    }
    atomicAdd(&sum[t], s);
    atomicAdd(&sq[t], q);
}

__global__ void k_finalize(const float* __restrict__ sum, const float* __restrict__ sq,
                           const float* __restrict__ gam, const float* __restrict__ bet,
                           float* __restrict__ a, float* __restrict__ c) {
    int t = threadIdx.x;
    const float invN = 1.0f / (float)NN;
    float mean = sum[t] * invN;
    float var  = sq[t] * invN - mean * mean;
    float inv  = rsqrtf(var + EPSV);
    float aa   = gam[t] * inv;
    a[t] = aa;
    c[t] = bet[t] - mean * aa;
}

__global__ void k_labels(const float* __restrict__ cid,
                         int* __restrict__ labels, int* __restrict__ cnt) {
    int m = blockIdx.x * blockDim.x + threadIdx.x;
    if (m >= MM) return;
    const float* row = cid + (size_t)m * KC;
    int best = 0;
    float bv = row[0];
#pragma unroll
    for (int k = 1; k < KC; k++) {
        float v = row[k];
        if (v > bv) { bv = v; best = k; }
    }
    labels[m] = best;
    atomicAdd(&cnt[best], 1);
}

// XC = relu(a2*H2[ci[m]] + c2): fp32 copy (for cluster sums) + tiled fp16
__global__ void k_make_xc(const float* __restrict__ H2, const int* __restrict__ ci,
                          const float* __restrict__ a2, const float* __restrict__ c2,
                          float* __restrict__ XC, __half* __restrict__ dst) {
    int idx = blockIdx.x * blockDim.x + threadIdx.x;
    if (idx >= MMP * (HF / 8)) return;
    int m = idx / (HF / 8);
    int k = (idx % (HF / 8)) * 8;
    __half h8[8];
    float o8[8];
#pragma unroll
    for (int j = 0; j < 8; j++) o8[j] = 0.f;
    if (m < MM) {
        int r = ci[m];
        const float* hp = H2 + (size_t)r * HF + k;
#pragma unroll
        for (int j = 0; j < 8; j++)
            o8[j] = fmaxf(fmaf(a2[k + j], hp[j], c2[k + j]), 0.f);
        float4* xp = (float4*)(XC + (size_t)m * HF + k);
        xp[0] = make_float4(o8[0], o8[1], o8[2], o8[3]);
        xp[1] = make_float4(o8[4], o8[5], o8[6], o8[7]);
    }
#pragma unroll
    for (int j = 0; j < 8; j++) h8[j] = __float2half(o8[j]);
    *(uint4*)(dst + tileoff(m, k, HF / 64)) = *(uint4*)h8;
}

__global__ void k_cluster_accum(const float* __restrict__ XC,
                                const int* __restrict__ labels,
                                float* __restrict__ CFsum) {
    __shared__ float acc[KC * HF];
    int t = threadIdx.x;
    for (int i = t; i < KC * HF; i += blockDim.x) acc[i] = 0.f;
    __syncthreads();
    int per = (MM + gridDim.x - 1) / gridDim.x;
    int m0 = blockIdx.x * per;
    int m1 = min(MM, m0 + per);
    for (int m = m0; m < m1; m++) {
        int lab = labels[m];
        acc[lab * HF + t] += XC[(size_t)m * HF + t];
    }
    __syncthreads();
    for (int i = t; i < KC * HF; i += blockDim.x) atomicAdd(&CFsum[i], acc[i]);
}

__global__ void k_ptab(const float* __restrict__ Wfc, const float* __restrict__ bfc,
                       const float* __restrict__ CFsum, const int* __restrict__ cnt,
                       float* __restrict__ PA, float* __restrict__ PB) {
    __shared__ float cf[HF];
    int k = blockIdx.y;
    int t = threadIdx.x;
    float cnv = (float)cnt[k];
    cf[t] = CFsum[k * HF + t] / cnv;
    __syncthreads();
    int o = blockIdx.x * 256 + t;
    const float* w = Wfc + (size_t)o * (2 * HF);
    float sa = 0.f, sb = 0.f;
#pragma unroll 4
    for (int j = 0; j < HF; j++) {
        float c = cf[j];
        sa = fmaf(c, w[j], sa);
        sb = fmaf(c, w[HF + j], sb);
    }
    float bb = bfc[o];
    PA[k * O2 + o] = sa + bb;
    PB[k * O2 + o] = sb + bb;
}

// ---------------- host launcher ---------------------------------------------
extern "C" void kernel_launch(void* const* d_in, const int* in_sizes, int n_in,
                              void* d_out, int out_size) {
    const float* x    = (const float*)d_in[0];
    const float* cid  = (const float*)d_in[1];
    const int*   cidx = (const int*)  d_in[2];
    const float* W1   = (const float*)d_in[3];
    const float* b1   = (const float*)d_in[4];
    const float* g1   = (const float*)d_in[5];
    const float* be1  = (const float*)d_in[6];
    const float* W2   = (const float*)d_in[7];
    const float* b2   = (const float*)d_in[8];
    const float* g2   = (const float*)d_in[9];
    const float* be2  = (const float*)d_in[10];
    const float* Wfc  = (const float*)d_in[11];
    const float* bfc  = (const float*)d_in[12];
    float* out = (float*)d_out;

    static bool inited = false;
    static float *H1, *H2, *XC, *sum1, *sq1, *a1, *c1, *sum2, *sq2, *a2, *c2,
                 *CFs, *PA, *PB;
    static int *cnt, *labs;
    static __half *xh, *W1h, *W1l, *A2h, *W2h, *W2l, *XCh, *WCh, *WCl;
    if (!inited) {
        inited = true;
        cudaGetSymbolAddress((void**)&H1,   g_H1);
        cudaGetSymbolAddress((void**)&H2,   g_H2);
        cudaGetSymbolAddress((void**)&XC,   g_XC);
        cudaGetSymbolAddress((void**)&sum1, g_sum1);
        cudaGetSymbolAddress((void**)&sq1,  g_sq1);
        cudaGetSymbolAddress((void**)&a1,   g_a1);
        cudaGetSymbolAddress((void**)&c1,   g_c1);
        cudaGetSymbolAddress((void**)&sum2, g_sum2);
        cudaGetSymbolAddress((void**)&sq2,  g_sq2);
        cudaGetSymbolAddress((void**)&a2,   g_a2);
        cudaGetSymbolAddress((void**)&c2,   g_c2);
        cudaGetSymbolAddress((void**)&CFs,  g_CFsum);
        cudaGetSymbolAddress((void**)&PA,   g_PA);
        cudaGetSymbolAddress((void**)&PB,   g_PB);
        cudaGetSymbolAddress((void**)&cnt,  g_counts);
        cudaGetSymbolAddress((void**)&labs, g_labels);
        cudaGetSymbolAddress((void**)&xh,   g_xh);
        cudaGetSymbolAddress((void**)&W1h,  g_W1h);
        cudaGetSymbolAddress((void**)&W1l,  g_W1l);
        cudaGetSymbolAddress((void**)&A2h,  g_A2h);
        cudaGetSymbolAddress((void**)&W2h,  g_W2h);
        cudaGetSymbolAddress((void**)&W2l,  g_W2l);
        cudaGetSymbolAddress((void**)&XCh,  g_XCh);
        cudaGetSymbolAddress((void**)&WCh,  g_WCh);
        cudaGetSymbolAddress((void**)&WCl,  g_WCl);
        cudaFuncSetAttribute(k_bulkmma<0>,
                             cudaFuncAttributeMaxDynamicSharedMemorySize, SMEM_GG);
        cudaFuncSetAttribute(k_bulkmma<1>,
                             cudaFuncAttributeMaxDynamicSharedMemorySize, SMEM_GG);
    }

    // 0) zero accumulators
    k_zero<<<40, 256>>>(sum1, sq1, sum2, sq2, CFs, cnt);

    // weight splits (B-side: hi/lo)
    {
        long long t1 = (long long)HF * (KP1 / 8);
        k_split_b<<<cdiv_h((int)t1, 256), 256>>>(W1, W1h, W1l,
                                                 HF, D_IN, KP1 / 8, KP1 / 64, t1);
        long long t2 = (long long)HF * (HF / 8);
        k_split_b<<<cdiv_h((int)t2, 256), 256>>>(W2, W2h, W2l,
                                                 HF, HF, HF / 8, HF / 64, t2);
        k_split_wcat<<<cdiv_h(2048 * (HF / 8), 256), 256>>>(Wfc, WCh, WCl);
    }
    // x (A-side: single fp16, rows padded to NNP, K padded to 512)
    {
        long long t = (long long)NNP * (KP1 / 8);
        k_split_a<<<(int)((t + 255) / 256), 256>>>(x, xh,
                                                   NN, D_IN, KP1 / 8, KP1 / 64, t);
    }

    // 1) H1 = x @ W1^T + b1
    {
        dim3 grid(HF / 128, NNP / 128);
        k_bulkmma<0><<<grid, 256, SMEM_GG>>>(xh, W1h, W1l,
            NN, HF, KP1 / 64, b1, H1, nullptr, nullptr, nullptr, nullptr);
    }
    // 2) BN1 stats (standalone, proven)
    k_colstats<<<512, 256>>>(H1, sum1, sq1);
    k_finalize<<<1, 256>>>(sum1, sq1, g1, be1, a1, c1);

    // 3) A2 = relu(a1*H1 + c1) -> fp16; H2 = A2 @ W2^T + b2
    {
        long long t = (long long)NNP * (HF / 8);
        k_split_aff_a<<<(int)((t + 255) / 256), 256>>>(H1, a1, c1, A2h, NN, t);
        dim3 grid(HF / 128, NNP / 128);
        k_bulkmma<0><<<grid, 256, SMEM_GG>>>(A2h, W2h, W2l,
            NN, HF, HF / 64, b2, H2, nullptr, nullptr, nullptr, nullptr);
    }
    // 4) BN2 stats
    k_colstats<<<512, 256>>>(H2, sum2, sq2);
    k_finalize<<<1, 256>>>(sum2, sq2, g2, be2, a2, c2);

    // 5) labels + counts
    k_labels<<<cdiv_h(MM, 256), 256>>>(cid, labs, cnt);

    // 6) XC = relu(a2 * H2[cidx] + c2): fp32 + fused fp16 tiling
    k_make_xc<<<cdiv_h(MMP * (HF / 8), 256), 256>>>(H2, cidx, a2, c2, XC, XCh);

    // 7) cluster feature sums
    k_cluster_accum<<<256, 256>>>(XC, labs, CFs);

    // 8) PA/PB tables
    {
        dim3 grid(O2 / 256, KC);
        k_ptab<<<grid, 256>>>(Wfc, bfc, CFs, cnt, PA, PB);
    }

    // 9) final GEMM: Y = XC @ Wcat^T, epilogue adds PB/PA and scatters rows
    {
        dim3 grid(2048 / 128, MMP / 128);
        k_bulkmma<1><<<grid, 256, SMEM_GG>>>(XCh, WCh, WCl,
            MM, 2048, HF / 64, nullptr, nullptr, labs, PA, PB, out);
    }
}

// round 12
// speedup vs baseline: 1.5868x; 1.1781x over previous
#include <cuda_runtime.h>
#include <cuda_fp16.h>
#include <cstdint>

// ---------------- problem constants ----------------------------------------
#define NN   100000   // batch rows
#define NNP  100096   // padded to 128
#define D_IN 500      // input features
#define KP1  512      // D_IN padded to MMA K granularity
#define HF   256      // hidden
#define MM   50000    // cluster rows
#define MMP  50048    // padded to 128
#define KC   40       // clusters
#define O2   1024     // OUT*OUT
#define EPSV 1e-5f

static inline int cdiv_h(int a, int b) { return (a + b - 1) / b; }

// ---------------- device scratch --------------------------------------------
__device__ float g_H1[(size_t)NN * HF];
__device__ float g_H2[(size_t)NN * HF];
__device__ float g_XC[(size_t)MM * HF];
__device__ float g_sum1[HF], g_sq1[HF], g_a1[HF], g_c1[HF];
__device__ float g_sum2[HF], g_sq2[HF], g_a2[HF], g_c2[HF];
__device__ float g_CFsum[KC * HF];
__device__ int   g_counts[KC];
__device__ int   g_labels[MM];
__device__ float g_PA[KC * O2];
__device__ float g_PB[KC * O2];

// Pre-tiled, SW128-swizzled fp16 operands (plain fp16, both sides).
// Tile (rowTile, kTile) of 128x64 halfs = 16 KB contiguous; SW128 inside.
__device__ __half g_xh [(size_t)NNP * KP1];
__device__ __half g_W1h[(size_t)HF * KP1];
__device__ __half g_A2h[(size_t)NNP * HF];
__device__ __half g_W2h[(size_t)HF * HF];
__device__ __half g_XCh[(size_t)MMP * HF];
__device__ __half g_WCh[(size_t)2048 * HF];

// ---------------- low-level helpers ------------------------------------------
__device__ __forceinline__ uint32_t smem_u32(const void* p) {
    uint32_t a;
    asm("{ .reg .u64 t; cvta.to.shared.u64 t, %1; cvt.u32.u64 %0, t; }"
        : "=r"(a) : "l"(p));
    return a;
}

__device__ __forceinline__ void bulkcp(uint32_t dst, const void* src,
                                       uint32_t bytes, uint32_t mbar) {
    asm volatile(
        "cp.async.bulk.shared::cluster.global.mbarrier::complete_tx::bytes "
        "[%0], [%1], %2, [%3];"
        :: "r"(dst), "l"(src), "r"(bytes), "r"(mbar) : "memory");
}

#define MBAR_INIT(addr, cnt) \
    asm volatile("mbarrier.init.shared.b64 [%0], %1;" \
                 :: "r"((uint32_t)(addr)), "r"((uint32_t)(cnt)) : "memory")
#define MBAR_EXPECT(addr, tx) \
    asm volatile("mbarrier.arrive.expect_tx.shared.b64 _, [%0], %1;" \
                 :: "r"((uint32_t)(addr)), "r"((uint32_t)(tx)) : "memory")
#define MBAR_WAIT(addr, parity) do {                                           \
    uint32_t _m = (uint32_t)(addr); uint32_t _p = (uint32_t)(parity);          \
    uint32_t _d;                                                               \
    asm volatile("{\n\t.reg .pred p;\n\t"                                      \
        "mbarrier.try_wait.parity.acquire.cta.shared::cta.b64 p, [%1], %2;\n\t"\
        "selp.b32 %0, 1, 0, p;\n\t}" : "=r"(_d) : "r"(_m), "r"(_p) : "memory");\
    if (!_d) {                                                                 \
        asm volatile("{\n\t.reg .pred P1;\n\t"                                 \
            "WL_%=:\n\t"                                                       \
            "mbarrier.try_wait.parity.acquire.cta.shared::cta.b64 P1, [%0], %1, 0x989680;\n\t" \
            "@P1 bra.uni WD_%=;\n\t"                                           \
            "bra.uni WL_%=;\n\t"                                               \
            "WD_%=:\n\t}" :: "r"(_m), "r"(_p) : "memory");                     \
    }                                                                          \
} while (0)

__device__ __forceinline__ void ldsm4(uint32_t* r, uint32_t addr) {
    asm volatile("ldmatrix.sync.aligned.m8n8.x4.shared.b16 {%0,%1,%2,%3}, [%4];"
                 : "=r"(r[0]), "=r"(r[1]), "=r"(r[2]), "=r"(r[3]) : "r"(addr));
}

__device__ __forceinline__ void mma16816(float* d, const uint32_t* a,
                                         uint32_t b0, uint32_t b1) {
    asm volatile(
        "mma.sync.aligned.m16n8k16.row.col.f32.f16.f16.f32 "
        "{%0,%1,%2,%3}, {%4,%5,%6,%7}, {%8,%9}, {%0,%1,%2,%3};"
        : "+f"(d[0]), "+f"(d[1]), "+f"(d[2]), "+f"(d[3])
        : "r"(a[0]), "r"(a[1]), "r"(a[2]), "r"(a[3]), "r"(b0), "r"(b1));
}

// Element offset inside the tiled+swizzled operand layout.
__device__ __forceinline__ size_t tileoff(int row, int k, int KT) {
    size_t base = ((size_t)((row >> 7) * KT + (k >> 6))) << 13;
    uint32_t boff = ((uint32_t)(row & 127) << 7) | ((uint32_t)(k & 63) << 1);
    uint32_t sw = boff ^ ((boff >> 3) & 0x70);
    return base + (sw >> 1);
}

__device__ __forceinline__ uint32_t swz(uint32_t boff) {
    return boff ^ ((boff >> 3) & 0x70);
}

// ---------------- bulk-loaded tensor-core GEMM (pure fp16) -------------------
// C = A[M,K] @ B[N,K]^T.  Stage = {A, B} 16 KB tiles (32 KB).
// MODE 0: C[r*Ncols+c] = acc + bias[c]
// MODE 1: layer-3 epilogue: +PB/PA[label] table, 2M-row output layout.
#define TILE16K 16384
#define STG32K  32768
#define NSTAGE  5
#define SMEM_GG (NSTAGE * STG32K + 48)

template <int MODE>
__global__ void __launch_bounds__(256)
k_bulkmma(const __half* __restrict__ Ah_, const __half* __restrict__ Bh_,
          int Mrows, int Ncols, int KT,
          const float* __restrict__ bias, float* __restrict__ Cmat,
          const int* __restrict__ labels, const float* __restrict__ PA,
          const float* __restrict__ PB, float* __restrict__ out) {
    extern __shared__ unsigned char smem[];
    const uint32_t sb = smem_u32(smem);
    const uint32_t mb = sb + NSTAGE * STG32K;   // mbarriers, 8 B apart
    const int tx = threadIdx.x;
    const int lane = tx & 31, wid = tx >> 5;
    const int warpM = wid & 3;           // 4 warps over M (32 rows each)
    const int warpN = wid >> 2;          // 2 warps over N (64 cols each)
    const int rowBase = blockIdx.y * 128;
    const int colBase = blockIdx.x * 128;

    if (tx == 0) {
#pragma unroll
        for (int s = 0; s < NSTAGE; s++) MBAR_INIT(mb + 8 * s, 1);
    }
    __syncthreads();

    const size_t aBase = ((size_t)blockIdx.y * KT) << 13;
    const size_t bBase = ((size_t)blockIdx.x * KT) << 13;

    if (tx == 0) {
        const int pre = (KT < NSTAGE) ? KT : NSTAGE;
        for (int s = 0; s < pre; s++) {
            MBAR_EXPECT(mb + 8 * s, STG32K);
            uint32_t d = sb + (uint32_t)s * STG32K;
            bulkcp(d + 0 * TILE16K, Ah_ + aBase + ((size_t)s << 13), TILE16K, mb + 8 * s);
            bulkcp(d + 1 * TILE16K, Bh_ + bBase + ((size_t)s << 13), TILE16K, mb + 8 * s);
        }
    }

    float acc[2][8][4];
#pragma unroll
    for (int i = 0; i < 2; i++)
#pragma unroll
        for (int j = 0; j < 8; j++)
#pragma unroll
            for (int q = 0; q < 4; q++) acc[i][j][q] = 0.f;

    int ph[NSTAGE] = {0, 0, 0, 0, 0};
    for (int c = 0; c < KT; c++) {
        const int s = c % NSTAGE;
        MBAR_WAIT(mb + 8 * s, ph[s]);
        ph[s] ^= 1;
        const uint32_t stg = sb + (uint32_t)s * STG32K;
#pragma unroll
        for (int ks = 0; ks < 4; ks++) {
            const int k0 = ks * 16;
            uint32_t ah[2][4], bh[4][4];
#pragma unroll
            for (int mf = 0; mf < 2; mf++) {
                uint32_t boff = ((uint32_t)(warpM * 32 + mf * 16 + (lane & 15)) << 7) |
                                ((uint32_t)(k0 + (lane >> 4) * 8) << 1);
                ldsm4(ah[mf], stg + 0 * TILE16K + swz(boff));
            }
            {
                const int grp = lane >> 3, rin = lane & 7;
#pragma unroll
                for (int p = 0; p < 4; p++) {
                    uint32_t boff = ((uint32_t)(warpN * 64 + p * 16 + (grp >> 1) * 8 + rin) << 7) |
                                    ((uint32_t)(k0 + (grp & 1) * 8) << 1);
                    ldsm4(bh[p], stg + 1 * TILE16K + swz(boff));
                }
            }
#pragma unroll
            for (int p = 0; p < 4; p++)
#pragma unroll
                for (int mf = 0; mf < 2; mf++) {
                    mma16816(acc[mf][2 * p + 0], ah[mf], bh[p][0], bh[p][1]);
                    mma16816(acc[mf][2 * p + 1], ah[mf], bh[p][2], bh[p][3]);
                }
        }
        __syncthreads();
        if (c + NSTAGE < KT && tx == 0) {
            const int cn = c + NSTAGE;
            MBAR_EXPECT(mb + 8 * s, STG32K);
            uint32_t d = sb + (uint32_t)s * STG32K;
            bulkcp(d + 0 * TILE16K, Ah_ + aBase + ((size_t)cn << 13), TILE16K, mb + 8 * s);
            bulkcp(d + 1 * TILE16K, Bh_ + bBase + ((size_t)cn << 13), TILE16K, mb + 8 * s);
        }
    }

    // ---------------- epilogue ----------------
#pragma unroll
    for (int mf = 0; mf < 2; mf++) {
#pragma unroll
        for (int half = 0; half < 2; half++) {
            const int r = rowBase + warpM * 32 + mf * 16 + (lane >> 2) + half * 8;
            if (r >= Mrows) continue;
            if (MODE == 0) {
                float* cp = Cmat + (size_t)r * Ncols;
#pragma unroll
                for (int nf = 0; nf < 8; nf++) {
                    const int cc = colBase + warpN * 64 + nf * 8 + (lane & 3) * 2;
                    float2 b = *(const float2*)(bias + cc);
                    float2 v;
                    v.x = acc[mf][nf][half * 2 + 0] + b.x;
                    v.y = acc[mf][nf][half * 2 + 1] + b.y;
                    *(float2*)(cp + cc) = v;
                }
            } else {
                const bool hB = colBase >= 1024;   // Wcat rows >=1024 = WfcB half
                const int lab = labels[r];
                const float* P = hB ? PA : PB;
                const float* pl = P + (size_t)lab * O2;
                float* op = out + ((size_t)r + (hB ? (size_t)MM : 0)) * O2;
                const int cB = (colBase & 1023) + warpN * 64;
#pragma unroll
                for (int nf = 0; nf < 8; nf++) {
                    const int col = cB + nf * 8 + (lane & 3) * 2;
                    float2 p = *(const float2*)(pl + col);
                    float2 v;
                    v.x = acc[mf][nf][half * 2 + 0] + p.x;
                    v.y = acc[mf][nf][half * 2 + 1] + p.y;
                    *(float2*)(op + col) = v;
                }
            }
        }
    }
}

// ---------------- split kernels: fp32 -> tiled swizzled fp16 ----------------
__global__ void k_split_a(const float* __restrict__ src,
                          __half* __restrict__ dst,
                          int rowsSrc, int colsSrc, int K8, int KT,
                          long long total) {
    long long idx = blockIdx.x * (long long)blockDim.x + threadIdx.x;
    if (idx >= total) return;
    int row = (int)(idx / K8);
    int k   = (int)(idx % K8) * 8;
    __half h8[8];
#pragma unroll
    for (int j = 0; j < 8; j++) {
        float v = 0.f;
        if (row < rowsSrc && k + j < colsSrc)
            v = src[(size_t)row * colsSrc + k + j];
        h8[j] = __float2half(v);
    }
    *(uint4*)(dst + tileoff(row, k, KT)) = *(uint4*)h8;
}

__global__ void k_split_aff_a(const float* __restrict__ src,
                              const float* __restrict__ aa, const float* __restrict__ cc,
                              __half* __restrict__ dst,
                              int rowsSrc, long long total) {
    long long idx = blockIdx.x * (long long)blockDim.x + threadIdx.x;
    if (idx >= total) return;
    int row = (int)(idx / (HF / 8));
    int k   = (int)(idx % (HF / 8)) * 8;
    __half h8[8];
#pragma unroll
    for (int j = 0; j < 8; j++) {
        float v = 0.f;
        if (row < rowsSrc)
            v = fmaxf(fmaf(aa[k + j], src[(size_t)row * HF + k + j], cc[k + j]), 0.f);
        h8[j] = __float2half(v);
    }
    *(uint4*)(dst + tileoff(row, k, HF / 64)) = *(uint4*)h8;
}

// Wcat[2048,256]: rows 0..1023 = Wfc[:, :256]; rows 1024..2047 = Wfc[:, 256:]
__global__ void k_split_wcat(const float* __restrict__ Wfc,
                             __half* __restrict__ dst) {
    int idx = blockIdx.x * blockDim.x + threadIdx.x;
    if (idx >= 2048 * (HF / 8)) return;
    int o = idx / (HF / 8);
    int k = (idx % (HF / 8)) * 8;
    const float* w = (o < 1024) ? (Wfc + (size_t)o * (2 * HF))
                                : (Wfc + (size_t)(o - 1024) * (2 * HF) + HF);
    __half h8[8];
#pragma unroll
    for (int j = 0; j < 8; j++) h8[j] = __float2half(w[k + j]);
    *(uint4*)(dst + tileoff(o, k, HF / 64)) = *(uint4*)h8;
}

// ---------------- stats / labels / segment mean ------------------------------
__global__ void k_zero(float* s1, float* q1, float* s2, float* q2,
                       float* cfs, int* cnt) {
    int t = blockIdx.x * blockDim.x + threadIdx.x;
    if (t < HF) { s1[t] = 0.f; q1[t] = 0.f; s2[t] = 0.f; q2[t] = 0.f; }
    if (t < KC) cnt[t] = 0;
    if (t < KC * HF) cfs[t] = 0.f;
}

__global__ void k_colstats(const float* __restrict__ H,
                           float* __restrict__ sum, float* __restrict__ sq) {
    int t = threadIdx.x;
    int per = (NN + gridDim.x - 1) / gridDim.x;
    int r0 = blockIdx.x * per;
    int r1 = min(NN, r0 + per);
    float s = 0.f, q = 0.f;
    for (int r = r0; r < r1; r++) {
        float v = H[(size_t)r * HF + t];
        s += v;
        q = fmaf(v, v, q);
    }
    atomicAdd(&sum[t], s);
    atomicAdd(&sq[t], q);
}

__global__ void k_finalize(const float* __restrict__ sum, const float* __restrict__ sq,
                           const float* __restrict__ gam, const float* __restrict__ bet,
                           float* __restrict__ a, float* __restrict__ c) {
    int t = threadIdx.x;
    const float invN = 1.0f / (float)NN;
    float mean = sum[t] * invN;
    float var  = sq[t] * invN - mean * mean;
    float inv  = rsqrtf(var + EPSV);
    float aa   = gam[t] * inv;
    a[t] = aa;
    c[t] = bet[t] - mean * aa;
}

__global__ void k_labels(const float* __restrict__ cid,
                         int* __restrict__ labels, int* __restrict__ cnt) {
    int m = blockIdx.x * blockDim.x + threadIdx.x;
    if (m >= MM) return;
    const float* row = cid + (size_t)m * KC;
    int best = 0;
    float bv = row[0];
#pragma unroll
    for (int k = 1; k < KC; k++) {
        float v = row[k];
        if (v > bv) { bv = v; best = k; }
    }
    labels[m] = best;
    atomicAdd(&cnt[best], 1);
}

// XC = relu(a2*H2[ci[m]] + c2): fp32 copy (for cluster sums) + tiled fp16
__global__ void k_make_xc(const float* __restrict__ H2, const int* __restrict__ ci,
                          const float* __restrict__ a2, const float* __restrict__ c2,
                          float* __restrict__ XC, __half* __restrict__ dst) {
    int idx = blockIdx.x * blockDim.x + threadIdx.x;
    if (idx >= MMP * (HF / 8)) return;
    int m = idx / (HF / 8);
    int k = (idx % (HF / 8)) * 8;
    __half h8[8];
    float o8[8];
#pragma unroll
    for (int j = 0; j < 8; j++) o8[j] = 0.f;
    if (m < MM) {
        int r = ci[m];
        const float* hp = H2 + (size_t)r * HF + k;
#pragma unroll
        for (int j = 0; j < 8; j++)
            o8[j] = fmaxf(fmaf(a2[k + j], hp[j], c2[k + j]), 0.f);
        float4* xp = (float4*)(XC + (size_t)m * HF + k);
        xp[0] = make_float4(o8[0], o8[1], o8[2], o8[3]);
        xp[1] = make_float4(o8[4], o8[5], o8[6], o8[7]);
    }
#pragma unroll
    for (int j = 0; j < 8; j++) h8[j] = __float2half(o8[j]);
    *(uint4*)(dst + tileoff(m, k, HF / 64)) = *(uint4*)h8;
}

__global__ void k_cluster_accum(const float* __restrict__ XC,
                                const int* __restrict__ labels,
                                float* __restrict__ CFsum) {
    __shared__ float acc[KC * HF];
    int t = threadIdx.x;
    for (int i = t; i < KC * HF; i += blockDim.x) acc[i] = 0.f;
    __syncthreads();
    int per = (MM + gridDim.x - 1) / gridDim.x;
    int m0 = blockIdx.x * per;
    int m1 = min(MM, m0 + per);
    for (int m = m0; m < m1; m++) {
        int lab = labels[m];
        acc[lab * HF + t] += XC[(size_t)m * HF + t];
    }
    __syncthreads();
    for (int i = t; i < KC * HF; i += blockDim.x) atomicAdd(&CFsum[i], acc[i]);
}

__global__ void k_ptab(const float* __restrict__ Wfc, const float* __restrict__ bfc,
                       const float* __restrict__ CFsum, const int* __restrict__ cnt,
                       float* __restrict__ PA, float* __restrict__ PB) {
    __shared__ float cf[HF];
    int k = blockIdx.y;
    int t = threadIdx.x;
    float cnv = (float)cnt[k];
    cf[t] = CFsum[k * HF + t] / cnv;
    __syncthreads();
    int o = blockIdx.x * 256 + t;
    const float* w = Wfc + (size_t)o * (2 * HF);
    float sa = 0.f, sb = 0.f;
#pragma unroll 4
    for (int j = 0; j < HF; j++) {
        float c = cf[j];
        sa = fmaf(c, w[j], sa);
        sb = fmaf(c, w[HF + j], sb);
    }
    float bb = bfc[o];
    PA[k * O2 + o] = sa + bb;
    PB[k * O2 + o] = sb + bb;
}

// ---------------- host launcher ---------------------------------------------
extern "C" void kernel_launch(void* const* d_in, const int* in_sizes, int n_in,
                              void* d_out, int out_size) {
    const float* x    = (const float*)d_in[0];
    const float* cid  = (const float*)d_in[1];
    const int*   cidx = (const int*)  d_in[2];
    const float* W1   = (const float*)d_in[3];
    const float* b1   = (const float*)d_in[4];
    const float* g1   = (const float*)d_in[5];
    const float* be1  = (const float*)d_in[6];
    const float* W2   = (const float*)d_in[7];
    const float* b2   = (const float*)d_in[8];
    const float* g2   = (const float*)d_in[9];
    const float* be2  = (const float*)d_in[10];
    const float* Wfc  = (const float*)d_in[11];
    const float* bfc  = (const float*)d_in[12];
    float* out = (float*)d_out;

    static bool inited = false;
    static float *H1, *H2, *XC, *sum1, *sq1, *a1, *c1, *sum2, *sq2, *a2, *c2,
                 *CFs, *PA, *PB;
    static int *cnt, *labs;
    static __half *xh, *W1h, *A2h, *W2h, *XCh, *WCh;
    if (!inited) {
        inited = true;
        cudaGetSymbolAddress((void**)&H1,   g_H1);
        cudaGetSymbolAddress((void**)&H2,   g_H2);
        cudaGetSymbolAddress((void**)&XC,   g_XC);
        cudaGetSymbolAddress((void**)&sum1, g_sum1);
        cudaGetSymbolAddress((void**)&sq1,  g_sq1);
        cudaGetSymbolAddress((void**)&a1,   g_a1);
        cudaGetSymbolAddress((void**)&c1,   g_c1);
        cudaGetSymbolAddress((void**)&sum2, g_sum2);
        cudaGetSymbolAddress((void**)&sq2,  g_sq2);
        cudaGetSymbolAddress((void**)&a2,   g_a2);
        cudaGetSymbolAddress((void**)&c2,   g_c2);
        cudaGetSymbolAddress((void**)&CFs,  g_CFsum);
        cudaGetSymbolAddress((void**)&PA,   g_PA);
        cudaGetSymbolAddress((void**)&PB,   g_PB);
        cudaGetSymbolAddress((void**)&cnt,  g_counts);
        cudaGetSymbolAddress((void**)&labs, g_labels);
        cudaGetSymbolAddress((void**)&xh,   g_xh);
        cudaGetSymbolAddress((void**)&W1h,  g_W1h);
        cudaGetSymbolAddress((void**)&A2h,  g_A2h);
        cudaGetSymbolAddress((void**)&W2h,  g_W2h);
        cudaGetSymbolAddress((void**)&XCh,  g_XCh);
        cudaGetSymbolAddress((void**)&WCh,  g_WCh);
        cudaFuncSetAttribute(k_bulkmma<0>,
                             cudaFuncAttributeMaxDynamicSharedMemorySize, SMEM_GG);
        cudaFuncSetAttribute(k_bulkmma<1>,
                             cudaFuncAttributeMaxDynamicSharedMemorySize, SMEM_GG);
    }

    // 0) zero accumulators
    k_zero<<<40, 256>>>(sum1, sq1, sum2, sq2, CFs, cnt);

    // weight conversions (plain fp16, tiled+swizzled)
    {
        long long t1 = (long long)HF * (KP1 / 8);
        k_split_a<<<cdiv_h((int)t1, 256), 256>>>(W1, W1h,
                                                 HF, D_IN, KP1 / 8, KP1 / 64, t1);
        long long t2 = (long long)HF * (HF / 8);
        k_split_a<<<cdiv_h((int)t2, 256), 256>>>(W2, W2h,
                                                 HF, HF, HF / 8, HF / 64, t2);
        k_split_wcat<<<cdiv_h(2048 * (HF / 8), 256), 256>>>(Wfc, WCh);
    }
    // x (rows padded to NNP, K padded to 512)
    {
        long long t = (long long)NNP * (KP1 / 8);
        k_split_a<<<(int)((t + 255) / 256), 256>>>(x, xh,
                                                   NN, D_IN, KP1 / 8, KP1 / 64, t);
    }

    // 1) H1 = x @ W1^T + b1
    {
        dim3 grid(HF / 128, NNP / 128);
        k_bulkmma<0><<<grid, 256, SMEM_GG>>>(xh, W1h,
            NN, HF, KP1 / 64, b1, H1, nullptr, nullptr, nullptr, nullptr);
    }
    // 2) BN1 stats
    k_colstats<<<512, 256>>>(H1, sum1, sq1);
    k_finalize<<<1, 256>>>(sum1, sq1, g1, be1, a1, c1);

    // 3) A2 = relu(a1*H1 + c1) -> fp16; H2 = A2 @ W2^T + b2
    {
        long long t = (long long)NNP * (HF / 8);
        k_split_aff_a<<<(int)((t + 255) / 256), 256>>>(H1, a1, c1, A2h, NN, t);
        dim3 grid(HF / 128, NNP / 128);
        k_bulkmma<0><<<grid, 256, SMEM_GG>>>(A2h, W2h,
            NN, HF, HF / 64, b2, H2, nullptr, nullptr, nullptr, nullptr);
    }
    // 4) BN2 stats
    k_colstats<<<512, 256>>>(H2, sum2, sq2);
    k_finalize<<<1, 256>>>(sum2, sq2, g2, be2, a2, c2);

    // 5) labels + counts
    k_labels<<<cdiv_h(MM, 256), 256>>>(cid, labs, cnt);

    // 6) XC = relu(a2 * H2[cidx] + c2): fp32 + fused fp16 tiling
    k_make_xc<<<cdiv_h(MMP * (HF / 8), 256), 256>>>(H2, cidx, a2, c2, XC, XCh);

    // 7) cluster feature sums
    k_cluster_accum<<<256, 256>>>(XC, labs, CFs);

    // 8) PA/PB tables (fp32 path — keeps the table exact)
    {
        dim3 grid(O2 / 256, KC);
        k_ptab<<<grid, 256>>>(Wfc, bfc, CFs, cnt, PA, PB);
    }

    // 9) final GEMM: Y = XC @ Wcat^T, epilogue adds PB/PA and scatters rows
    {
        dim3 grid(2048 / 128, MMP / 128);
        k_bulkmma<1><<<grid, 256, SMEM_GG>>>(XCh, WCh,
            MM, 2048, HF / 64, nullptr, nullptr, labs, PA, PB, out);
    }
}

// round 13
// speedup vs baseline: 1.8344x; 1.1560x over previous
#include <cuda_runtime.h>
#include <cuda_fp16.h>
#include <cstdint>

// ---------------- problem constants ----------------------------------------
#define NN   100000   // batch rows
#define NNP  100096   // padded to 128
#define D_IN 500      // input features
#define KP1  512      // D_IN padded to MMA K granularity
#define HF   256      // hidden
#define MM   50000    // cluster rows
#define MMP  50048    // padded to 128
#define KC   40       // clusters
#define O2   1024     // OUT*OUT
#define EPSV 1e-5f

static inline int cdiv_h(int a, int b) { return (a + b - 1) / b; }

// ---------------- device scratch --------------------------------------------
__device__ float g_H1[(size_t)NN * HF];
__device__ float g_H2[(size_t)NN * HF];
__device__ float g_XC[(size_t)MM * HF];
__device__ float g_sum1[HF], g_sq1[HF], g_a1[HF], g_c1[HF];
__device__ float g_sum2[HF], g_sq2[HF], g_a2[HF], g_c2[HF];
__device__ float g_CFsum[KC * HF];
__device__ int   g_counts[KC];
__device__ int   g_labels[MM];
__device__ float g_PA[KC * O2];
__device__ float g_PB[KC * O2];

// Pre-tiled, SW128-swizzled fp16 operands (plain fp16, both sides).
// Tile (rowTile, kTile) of 128x64 halfs = 16 KB contiguous; SW128 inside.
__device__ __half g_xh [(size_t)NNP * KP1];
__device__ __half g_W1h[(size_t)HF * KP1];
__device__ __half g_A2h[(size_t)NNP * HF];
__device__ __half g_W2h[(size_t)HF * HF];
__device__ __half g_XCh[(size_t)MMP * HF];
__device__ __half g_WCh[(size_t)2048 * HF];

// ---------------- low-level helpers ------------------------------------------
__device__ __forceinline__ uint32_t smem_u32(const void* p) {
    uint32_t a;
    asm("{ .reg .u64 t; cvta.to.shared.u64 t, %1; cvt.u32.u64 %0, t; }"
        : "=r"(a) : "l"(p));
    return a;
}

__device__ __forceinline__ void bulkcp(uint32_t dst, const void* src,
                                       uint32_t bytes, uint32_t mbar) {
    asm volatile(
        "cp.async.bulk.shared::cluster.global.mbarrier::complete_tx::bytes "
        "[%0], [%1], %2, [%3];"
        :: "r"(dst), "l"(src), "r"(bytes), "r"(mbar) : "memory");
}

#define MBAR_INIT(addr, cnt) \
    asm volatile("mbarrier.init.shared.b64 [%0], %1;" \
                 :: "r"((uint32_t)(addr)), "r"((uint32_t)(cnt)) : "memory")
#define MBAR_EXPECT(addr, tx) \
    asm volatile("mbarrier.arrive.expect_tx.shared.b64 _, [%0], %1;" \
                 :: "r"((uint32_t)(addr)), "r"((uint32_t)(tx)) : "memory")
#define MBAR_WAIT(addr, parity) do {                                           \
    uint32_t _m = (uint32_t)(addr); uint32_t _p = (uint32_t)(parity);          \
    uint32_t _d;                                                               \
    asm volatile("{\n\t.reg .pred p;\n\t"                                      \
        "mbarrier.try_wait.parity.acquire.cta.shared::cta.b64 p, [%1], %2;\n\t"\
        "selp.b32 %0, 1, 0, p;\n\t}" : "=r"(_d) : "r"(_m), "r"(_p) : "memory");\
    if (!_d) {                                                                 \
        asm volatile("{\n\t.reg .pred P1;\n\t"                                 \
            "WL_%=:\n\t"                                                       \
            "mbarrier.try_wait.parity.acquire.cta.shared::cta.b64 P1, [%0], %1, 0x989680;\n\t" \
            "@P1 bra.uni WD_%=;\n\t"                                           \
            "bra.uni WL_%=;\n\t"                                               \
            "WD_%=:\n\t}" :: "r"(_m), "r"(_p) : "memory");                     \
    }                                                                          \
} while (0)

__device__ __forceinline__ void ldsm4(uint32_t* r, uint32_t addr) {
    asm volatile("ldmatrix.sync.aligned.m8n8.x4.shared.b16 {%0,%1,%2,%3}, [%4];"
                 : "=r"(r[0]), "=r"(r[1]), "=r"(r[2]), "=r"(r[3]) : "r"(addr));
}

__device__ __forceinline__ void mma16816(float* d, const uint32_t* a,
                                         uint32_t b0, uint32_t b1) {
    asm volatile(
        "mma.sync.aligned.m16n8k16.row.col.f32.f16.f16.f32 "
        "{%0,%1,%2,%3}, {%4,%5,%6,%7}, {%8,%9}, {%0,%1,%2,%3};"
        : "+f"(d[0]), "+f"(d[1]), "+f"(d[2]), "+f"(d[3])
        : "r"(a[0]), "r"(a[1]), "r"(a[2]), "r"(a[3]), "r"(b0), "r"(b1));
}

// Element offset inside the tiled+swizzled operand layout.
__device__ __forceinline__ size_t tileoff(int row, int k, int KT) {
    size_t base = ((size_t)((row >> 7) * KT + (k >> 6))) << 13;
    uint32_t boff = ((uint32_t)(row & 127) << 7) | ((uint32_t)(k & 63) << 1);
    uint32_t sw = boff ^ ((boff >> 3) & 0x70);
    return base + (sw >> 1);
}

__device__ __forceinline__ uint32_t swz(uint32_t boff) {
    return boff ^ ((boff >> 3) & 0x70);
}

// ---------------- bulk-loaded tensor-core GEMM (pure fp16) -------------------
// C = A[M,K] @ B[N,K]^T.  Stage = {A, B} 16 KB tiles (32 KB).
// NSTAGE=3 -> 96 KB/CTA -> 2 CTAs/SM: cross-CTA overlap hides per-chunk
// sync bubbles, prologue and epilogue (the R12 residual).
// MODE 0: C[r*Ncols+c] = acc + bias[c]
// MODE 1: layer-3 epilogue: +PB/PA[label] table, 2M-row output layout.
#define TILE16K 16384
#define STG32K  32768
#define NSTAGE  3
#define SMEM_GG (NSTAGE * STG32K + 48)

template <int MODE>
__global__ void __launch_bounds__(256, 2)
k_bulkmma(const __half* __restrict__ Ah_, const __half* __restrict__ Bh_,
          int Mrows, int Ncols, int KT,
          const float* __restrict__ bias, float* __restrict__ Cmat,
          const int* __restrict__ labels, const float* __restrict__ PA,
          const float* __restrict__ PB, float* __restrict__ out) {
    extern __shared__ unsigned char smem[];
    const uint32_t sb = smem_u32(smem);
    const uint32_t mb = sb + NSTAGE * STG32K;   // mbarriers, 8 B apart
    const int tx = threadIdx.x;
    const int lane = tx & 31, wid = tx >> 5;
    const int warpM = wid & 3;           // 4 warps over M (32 rows each)
    const int warpN = wid >> 2;          // 2 warps over N (64 cols each)
    const int rowBase = blockIdx.y * 128;
    const int colBase = blockIdx.x * 128;

    if (tx == 0) {
#pragma unroll
        for (int s = 0; s < NSTAGE; s++) MBAR_INIT(mb + 8 * s, 1);
    }
    __syncthreads();

    const size_t aBase = ((size_t)blockIdx.y * KT) << 13;
    const size_t bBase = ((size_t)blockIdx.x * KT) << 13;

    if (tx == 0) {
        const int pre = (KT < NSTAGE) ? KT : NSTAGE;
        for (int s = 0; s < pre; s++) {
            MBAR_EXPECT(mb + 8 * s, STG32K);
            uint32_t d = sb + (uint32_t)s * STG32K;
            bulkcp(d + 0 * TILE16K, Ah_ + aBase + ((size_t)s << 13), TILE16K, mb + 8 * s);
            bulkcp(d + 1 * TILE16K, Bh_ + bBase + ((size_t)s << 13), TILE16K, mb + 8 * s);
        }
    }

    float acc[2][8][4];
#pragma unroll
    for (int i = 0; i < 2; i++)
#pragma unroll
        for (int j = 0; j < 8; j++)
#pragma unroll
            for (int q = 0; q < 4; q++) acc[i][j][q] = 0.f;

    int ph[NSTAGE] = {0, 0, 0};
    for (int c = 0; c < KT; c++) {
        const int s = c % NSTAGE;
        MBAR_WAIT(mb + 8 * s, ph[s]);
        ph[s] ^= 1;
        const uint32_t stg = sb + (uint32_t)s * STG32K;
#pragma unroll
        for (int ks = 0; ks < 4; ks++) {
            const int k0 = ks * 16;
            uint32_t ah[2][4], bh[4][4];
#pragma unroll
            for (int mf = 0; mf < 2; mf++) {
                uint32_t boff = ((uint32_t)(warpM * 32 + mf * 16 + (lane & 15)) << 7) |
                                ((uint32_t)(k0 + (lane >> 4) * 8) << 1);
                ldsm4(ah[mf], stg + 0 * TILE16K + swz(boff));
            }
            {
                const int grp = lane >> 3, rin = lane & 7;
#pragma unroll
                for (int p = 0; p < 4; p++) {
                    uint32_t boff = ((uint32_t)(warpN * 64 + p * 16 + (grp >> 1) * 8 + rin) << 7) |
                                    ((uint32_t)(k0 + (grp & 1) * 8) << 1);
                    ldsm4(bh[p], stg + 1 * TILE16K + swz(boff));
                }
            }
#pragma unroll
            for (int p = 0; p < 4; p++)
#pragma unroll
                for (int mf = 0; mf < 2; mf++) {
                    mma16816(acc[mf][2 * p + 0], ah[mf], bh[p][0], bh[p][1]);
                    mma16816(acc[mf][2 * p + 1], ah[mf], bh[p][2], bh[p][3]);
                }
        }
        __syncthreads();
        if (c + NSTAGE < KT && tx == 0) {
            const int cn = c + NSTAGE;
            MBAR_EXPECT(mb + 8 * s, STG32K);
            uint32_t d = sb + (uint32_t)s * STG32K;
            bulkcp(d + 0 * TILE16K, Ah_ + aBase + ((size_t)cn << 13), TILE16K, mb + 8 * s);
            bulkcp(d + 1 * TILE16K, Bh_ + bBase + ((size_t)cn << 13), TILE16K, mb + 8 * s);
        }
    }

    // ---------------- epilogue ----------------
#pragma unroll
    for (int mf = 0; mf < 2; mf++) {
#pragma unroll
        for (int half = 0; half < 2; half++) {
            const int r = rowBase + warpM * 32 + mf * 16 + (lane >> 2) + half * 8;
            if (r >= Mrows) continue;
            if (MODE == 0) {
                float* cp = Cmat + (size_t)r * Ncols;
#pragma unroll
                for (int nf = 0; nf < 8; nf++) {
                    const int cc = colBase + warpN * 64 + nf * 8 + (lane & 3) * 2;
                    float2 b = *(const float2*)(bias + cc);
                    float2 v;
                    v.x = acc[mf][nf][half * 2 + 0] + b.x;
                    v.y = acc[mf][nf][half * 2 + 1] + b.y;
                    *(float2*)(cp + cc) = v;
                }
            } else {
                const bool hB = colBase >= 1024;   // Wcat rows >=1024 = WfcB half
                const int lab = labels[r];
                const float* P = hB ? PA : PB;
                const float* pl = P + (size_t)lab * O2;
                float* op = out + ((size_t)r + (hB ? (size_t)MM : 0)) * O2;
                const int cB = (colBase & 1023) + warpN * 64;
#pragma unroll
                for (int nf = 0; nf < 8; nf++) {
                    const int col = cB + nf * 8 + (lane & 3) * 2;
                    float2 p = *(const float2*)(pl + col);
                    float2 v;
                    v.x = acc[mf][nf][half * 2 + 0] + p.x;
                    v.y = acc[mf][nf][half * 2 + 1] + p.y;
                    *(float2*)(op + col) = v;
                }
            }
        }
    }
}

// ---------------- split kernels: fp32 -> tiled swizzled fp16 ----------------
__global__ void k_split_a(const float* __restrict__ src,
                          __half* __restrict__ dst,
                          int rowsSrc, int colsSrc, int K8, int KT,
                          long long total) {
    long long idx = blockIdx.x * (long long)blockDim.x + threadIdx.x;
    if (idx >= total) return;
    int row = (int)(idx / K8);
    int k   = (int)(idx % K8) * 8;
    __half h8[8];
#pragma unroll
    for (int j = 0; j < 8; j++) {
        float v = 0.f;
        if (row < rowsSrc && k + j < colsSrc)
            v = src[(size_t)row * colsSrc + k + j];
        h8[j] = __float2half(v);
    }
    *(uint4*)(dst + tileoff(row, k, KT)) = *(uint4*)h8;
}

__global__ void k_split_aff_a(const float* __restrict__ src,
                              const float* __restrict__ aa, const float* __restrict__ cc,
                              __half* __restrict__ dst,
                              int rowsSrc, long long total) {
    long long idx = blockIdx.x * (long long)blockDim.x + threadIdx.x;
    if (idx >= total) return;
    int row = (int)(idx / (HF / 8));
    int k   = (int)(idx % (HF / 8)) * 8;
    __half h8[8];
#pragma unroll
    for (int j = 0; j < 8; j++) {
        float v = 0.f;
        if (row < rowsSrc)
            v = fmaxf(fmaf(aa[k + j], src[(size_t)row * HF + k + j], cc[k + j]), 0.f);
        h8[j] = __float2half(v);
    }
    *(uint4*)(dst + tileoff(row, k, HF / 64)) = *(uint4*)h8;
}

// Wcat[2048,256]: rows 0..1023 = Wfc[:, :256]; rows 1024..2047 = Wfc[:, 256:]
__global__ void k_split_wcat(const float* __restrict__ Wfc,
                             __half* __restrict__ dst) {
    int idx = blockIdx.x * blockDim.x + threadIdx.x;
    if (idx >= 2048 * (HF / 8)) return;
    int o = idx / (HF / 8);
    int k = (idx % (HF / 8)) * 8;
    const float* w = (o < 1024) ? (Wfc + (size_t)o * (2 * HF))
                                : (Wfc + (size_t)(o - 1024) * (2 * HF) + HF);
    __half h8[8];
#pragma unroll
    for (int j = 0; j < 8; j++) h8[j] = __float2half(w[k + j]);
    *(uint4*)(dst + tileoff(o, k, HF / 64)) = *(uint4*)h8;
}

// ---------------- stats / labels / segment mean ------------------------------
__global__ void k_zero(float* s1, float* q1, float* s2, float* q2,
                       float* cfs, int* cnt) {
    int t = blockIdx.x * blockDim.x + threadIdx.x;
    if (t < HF) { s1[t] = 0.f; q1[t] = 0.f; s2[t] = 0.f; q2[t] = 0.f; }
    if (t < KC) cnt[t] = 0;
    if (t < KC * HF) cfs[t] = 0.f;
}

__global__ void k_colstats(const float* __restrict__ H,
                           float* __restrict__ sum, float* __restrict__ sq) {
    int t = threadIdx.x;
    int per = (NN + gridDim.x - 1) / gridDim.x;
    int r0 = blockIdx.x * per;
    int r1 = min(NN, r0 + per);
    float s = 0.f, q = 0.f;
    for (int r = r0; r < r1; r++) {
        float v = H[(size_t)r * HF + t];
        s += v;
        q = fmaf(v, v, q);
    }
    atomicAdd(&sum[t], s);
    atomicAdd(&sq[t], q);
}

__global__ void k_finalize(const float* __restrict__ sum, const float* __restrict__ sq,
                           const float* __restrict__ gam, const float* __restrict__ bet,
                           float* __restrict__ a, float* __restrict__ c) {
    int t = threadIdx.x;
    const float invN = 1.0f / (float)NN;
    float mean = sum[t] * invN;
    float var  = sq[t] * invN - mean * mean;
    float inv  = rsqrtf(var + EPSV);
    float aa   = gam[t] * inv;
    a[t] = aa;
    c[t] = bet[t] - mean * aa;
}

__global__ void k_labels(const float* __restrict__ cid,
                         int* __restrict__ labels, int* __restrict__ cnt) {
    int m = blockIdx.x * blockDim.x + threadIdx.x;
    if (m >= MM) return;
    const float* row = cid + (size_t)m * KC;
    int best = 0;
    float bv = row[0];
#pragma unroll
    for (int k = 1; k < KC; k++) {
        float v = row[k];
        if (v > bv) { bv = v; best = k; }
    }
    labels[m] = best;
    atomicAdd(&cnt[best], 1);
}

// XC = relu(a2*H2[ci[m]] + c2): fp32 copy (for cluster sums) + tiled fp16
__global__ void k_make_xc(const float* __restrict__ H2, const int* __restrict__ ci,
                          const float* __restrict__ a2, const float* __restrict__ c2,
                          float* __restrict__ XC, __half* __restrict__ dst) {
    int idx = blockIdx.x * blockDim.x + threadIdx.x;
    if (idx >= MMP * (HF / 8)) return;
    int m = idx / (HF / 8);
    int k = (idx % (HF / 8)) * 8;
    __half h8[8];
    float o8[8];
#pragma unroll
    for (int j = 0; j < 8; j++) o8[j] = 0.f;
    if (m < MM) {
        int r = ci[m];
        const float* hp = H2 + (size_t)r * HF + k;
#pragma unroll
        for (int j = 0; j < 8; j++)
            o8[j] = fmaxf(fmaf(a2[k + j], hp[j], c2[k + j]), 0.f);
        float4* xp = (float4*)(XC + (size_t)m * HF + k);
        xp[0] = make_float4(o8[0], o8[1], o8[2], o8[3]);
        xp[1] = make_float4(o8[4], o8[5], o8[6], o8[7]);
    }
#pragma unroll
    for (int j = 0; j < 8; j++) h8[j] = __float2half(o8[j]);
    *(uint4*)(dst + tileoff(m, k, HF / 64)) = *(uint4*)h8;
}

__global__ void k_cluster_accum(const float* __restrict__ XC,
                                const int* __restrict__ labels,
                                float* __restrict__ CFsum) {
    __shared__ float acc[KC * HF];
    int t = threadIdx.x;
    for (int i = t; i < KC * HF; i += blockDim.x) acc[i] = 0.f;
    __syncthreads();
    int per = (MM + gridDim.x - 1) / gridDim.x;
    int m0 = blockIdx.x * per;
    int m1 = min(MM, m0 + per);
    for (int m = m0; m < m1; m++) {
        int lab = labels[m];
        acc[lab * HF + t] += XC[(size_t)m * HF + t];
    }
    __syncthreads();
    for (int i = t; i < KC * HF; i += blockDim.x) atomicAdd(&CFsum[i], acc[i]);
}

__global__ void k_ptab(const float* __restrict__ Wfc, const float* __restrict__ bfc,
                       const float* __restrict__ CFsum, const int* __restrict__ cnt,
                       float* __restrict__ PA, float* __restrict__ PB) {
    __shared__ float cf[HF];
    int k = blockIdx.y;
    int t = threadIdx.x;
    float cnv = (float)cnt[k];
    cf[t] = CFsum[k * HF + t] / cnv;
    __syncthreads();
    int o = blockIdx.x * 256 + t;
    const float* w = Wfc + (size_t)o * (2 * HF);
    float sa = 0.f, sb = 0.f;
#pragma unroll 4
    for (int j = 0; j < HF; j++) {
        float c = cf[j];
        sa = fmaf(c, w[j], sa);
        sb = fmaf(c, w[HF + j], sb);
    }
    float bb = bfc[o];
    PA[k * O2 + o] = sa + bb;
    PB[k * O2 + o] = sb + bb;
}

// ---------------- host launcher ---------------------------------------------
extern "C" void kernel_launch(void* const* d_in, const int* in_sizes, int n_in,
                              void* d_out, int out_size) {
    const float* x    = (const float*)d_in[0];
    const float* cid  = (const float*)d_in[1];
    const int*   cidx = (const int*)  d_in[2];
    const float* W1   = (const float*)d_in[3];
    const float* b1   = (const float*)d_in[4];
    const float* g1   = (const float*)d_in[5];
    const float* be1  = (const float*)d_in[6];
    const float* W2   = (const float*)d_in[7];
    const float* b2   = (const float*)d_in[8];
    const float* g2   = (const float*)d_in[9];
    const float* be2  = (const float*)d_in[10];
    const float* Wfc  = (const float*)d_in[11];
    const float* bfc  = (const float*)d_in[12];
    float* out = (float*)d_out;

    static bool inited = false;
    static float *H1, *H2, *XC, *sum1, *sq1, *a1, *c1, *sum2, *sq2, *a2, *c2,
                 *CFs, *PA, *PB;
    static int *cnt, *labs;
    static __half *xh, *W1h, *A2h, *W2h, *XCh, *WCh;
    if (!inited) {
        inited = true;
        cudaGetSymbolAddress((void**)&H1,   g_H1);
        cudaGetSymbolAddress((void**)&H2,   g_H2);
        cudaGetSymbolAddress((void**)&XC,   g_XC);
        cudaGetSymbolAddress((void**)&sum1, g_sum1);
        cudaGetSymbolAddress((void**)&sq1,  g_sq1);
        cudaGetSymbolAddress((void**)&a1,   g_a1);
        cudaGetSymbolAddress((void**)&c1,   g_c1);
        cudaGetSymbolAddress((void**)&sum2, g_sum2);
        cudaGetSymbolAddress((void**)&sq2,  g_sq2);
        cudaGetSymbolAddress((void**)&a2,   g_a2);
        cudaGetSymbolAddress((void**)&c2,   g_c2);
        cudaGetSymbolAddress((void**)&CFs,  g_CFsum);
        cudaGetSymbolAddress((void**)&PA,   g_PA);
        cudaGetSymbolAddress((void**)&PB,   g_PB);
        cudaGetSymbolAddress((void**)&cnt,  g_counts);
        cudaGetSymbolAddress((void**)&labs, g_labels);
        cudaGetSymbolAddress((void**)&xh,   g_xh);
        cudaGetSymbolAddress((void**)&W1h,  g_W1h);
        cudaGetSymbolAddress((void**)&A2h,  g_A2h);
        cudaGetSymbolAddress((void**)&W2h,  g_W2h);
        cudaGetSymbolAddress((void**)&XCh,  g_XCh);
        cudaGetSymbolAddress((void**)&WCh,  g_WCh);
        cudaFuncSetAttribute(k_bulkmma<0>,
                             cudaFuncAttributeMaxDynamicSharedMemorySize, SMEM_GG);
        cudaFuncSetAttribute(k_bulkmma<1>,
                             cudaFuncAttributeMaxDynamicSharedMemorySize, SMEM_GG);
    }

    // 0) zero accumulators
    k_zero<<<40, 256>>>(sum1, sq1, sum2, sq2, CFs, cnt);

    // weight conversions (plain fp16, tiled+swizzled)
    {
        long long t1 = (long long)HF * (KP1 / 8);
        k_split_a<<<cdiv_h((int)t1, 256), 256>>>(W1, W1h,
                                                 HF, D_IN, KP1 / 8, KP1 / 64, t1);
        long long t2 = (long long)HF * (HF / 8);
        k_split_a<<<cdiv_h((int)t2, 256), 256>>>(W2, W2h,
                                                 HF, HF, HF / 8, HF / 64, t2);
        k_split_wcat<<<cdiv_h(2048 * (HF / 8), 256), 256>>>(Wfc, WCh);
    }
    // x (rows padded to NNP, K padded to 512)
    {
        long long t = (long long)NNP * (KP1 / 8);
        k_split_a<<<(int)((t + 255) / 256), 256>>>(x, xh,
                                                   NN, D_IN, KP1 / 8, KP1 / 64, t);
    }

    // 1) H1 = x @ W1^T + b1
    {
        dim3 grid(HF / 128, NNP / 128);
        k_bulkmma<0><<<grid, 256, SMEM_GG>>>(xh, W1h,
            NN, HF, KP1 / 64, b1, H1, nullptr, nullptr, nullptr, nullptr);
    }
    // 2) BN1 stats
    k_colstats<<<512, 256>>>(H1, sum1, sq1);
    k_finalize<<<1, 256>>>(sum1, sq1, g1, be1, a1, c1);

    // 3) A2 = relu(a1*H1 + c1) -> fp16; H2 = A2 @ W2^T + b2
    {
        long long t = (long long)NNP * (HF / 8);
        k_split_aff_a<<<(int)((t + 255) / 256), 256>>>(H1, a1, c1, A2h, NN, t);
        dim3 grid(HF / 128, NNP / 128);
        k_bulkmma<0><<<grid, 256, SMEM_GG>>>(A2h, W2h,
            NN, HF, HF / 64, b2, H2, nullptr, nullptr, nullptr, nullptr);
    }
    // 4) BN2 stats
    k_colstats<<<512, 256>>>(H2, sum2, sq2);
    k_finalize<<<1, 256>>>(sum2, sq2, g2, be2, a2, c2);

    // 5) labels + counts
    k_labels<<<cdiv_h(MM, 256), 256>>>(cid, labs, cnt);

    // 6) XC = relu(a2 * H2[cidx] + c2): fp32 + fused fp16 tiling
    k_make_xc<<<cdiv_h(MMP * (HF / 8), 256), 256>>>(H2, cidx, a2, c2, XC, XCh);

    // 7) cluster feature sums
    k_cluster_accum<<<256, 256>>>(XC, labs, CFs);

    // 8) PA/PB tables (fp32 path — keeps the table exact)
    {
        dim3 grid(O2 / 256, KC);
        k_ptab<<<grid, 256>>>(Wfc, bfc, CFs, cnt, PA, PB);
    }

    // 9) final GEMM: Y = XC @ Wcat^T, epilogue adds PB/PA and scatters rows
    {
        dim3 grid(2048 / 128, MMP / 128);
        k_bulkmma<1><<<grid, 256, SMEM_GG>>>(XCh, WCh,
            MM, 2048, HF / 64, nullptr, nullptr, labs, PA, PB, out);
    }
}

// round 14
// speedup vs baseline: 1.9718x; 1.0749x over previous
#include <cuda_runtime.h>
#include <cuda_fp16.h>
#include <cstdint>

// ---------------- problem constants ----------------------------------------
#define NN   100000   // batch rows
#define NNP  100096   // padded to 128
#define D_IN 500      // input features
#define KP1  512      // D_IN padded to MMA K granularity
#define HF   256      // hidden
#define MM   50000    // cluster rows
#define MMP  50048    // padded to 128
#define KC   40       // clusters
#define O2   1024     // OUT*OUT
#define EPSV 1e-5f

static inline int cdiv_h(int a, int b) { return (a + b - 1) / b; }

// ---------------- device scratch --------------------------------------------
__device__ __half g_H1[(size_t)NN * HF];    // raw GEMM1 out (fp16)
__device__ __half g_H2[(size_t)NN * HF];    // raw GEMM2 out (fp16)
__device__ float g_XC[(size_t)MM * HF];     // fp32 (protects cluster-mean path)
__device__ float g_sum1[HF], g_sq1[HF], g_a1[HF], g_c1[HF];
__device__ float g_sum2[HF], g_sq2[HF], g_a2[HF], g_c2[HF];
__device__ float g_CFsum[KC * HF];
__device__ int   g_counts[KC];
__device__ int   g_labels[MM];
__device__ float g_PA[KC * O2];
__device__ float g_PB[KC * O2];

// Pre-tiled, SW128-swizzled fp16 operands.
// Tile (rowTile, kTile) of 128x64 halfs = 16 KB contiguous; SW128 inside.
__device__ __half g_xh [(size_t)NNP * KP1];
__device__ __half g_W1h[(size_t)HF * KP1];
__device__ __half g_A2h[(size_t)NNP * HF];
__device__ __half g_W2h[(size_t)HF * HF];
__device__ __half g_XCh[(size_t)MMP * HF];
__device__ __half g_WCh[(size_t)2048 * HF];

// ---------------- low-level helpers ------------------------------------------
__device__ __forceinline__ uint32_t smem_u32(const void* p) {
    uint32_t a;
    asm("{ .reg .u64 t; cvta.to.shared.u64 t, %1; cvt.u32.u64 %0, t; }"
        : "=r"(a) : "l"(p));
    return a;
}

__device__ __forceinline__ void bulkcp(uint32_t dst, const void* src,
                                       uint32_t bytes, uint32_t mbar) {
    asm volatile(
        "cp.async.bulk.shared::cluster.global.mbarrier::complete_tx::bytes "
        "[%0], [%1], %2, [%3];"
        :: "r"(dst), "l"(src), "r"(bytes), "r"(mbar) : "memory");
}

#define MBAR_INIT(addr, cnt) \
    asm volatile("mbarrier.init.shared.b64 [%0], %1;" \
                 :: "r"((uint32_t)(addr)), "r"((uint32_t)(cnt)) : "memory")
#define MBAR_EXPECT(addr, tx) \
    asm volatile("mbarrier.arrive.expect_tx.shared.b64 _, [%0], %1;" \
                 :: "r"((uint32_t)(addr)), "r"((uint32_t)(tx)) : "memory")
#define MBAR_WAIT(addr, parity) do {                                           \
    uint32_t _m = (uint32_t)(addr); uint32_t _p = (uint32_t)(parity);          \
    uint32_t _d;                                                               \
    asm volatile("{\n\t.reg .pred p;\n\t"                                      \
        "mbarrier.try_wait.parity.acquire.cta.shared::cta.b64 p, [%1], %2;\n\t"\
        "selp.b32 %0, 1, 0, p;\n\t}" : "=r"(_d) : "r"(_m), "r"(_p) : "memory");\
    if (!_d) {                                                                 \
        asm volatile("{\n\t.reg .pred P1;\n\t"                                 \
            "WL_%=:\n\t"                                                       \
            "mbarrier.try_wait.parity.acquire.cta.shared::cta.b64 P1, [%0], %1, 0x989680;\n\t" \
            "@P1 bra.uni WD_%=;\n\t"                                           \
            "bra.uni WL_%=;\n\t"                                               \
            "WD_%=:\n\t}" :: "r"(_m), "r"(_p) : "memory");                     \
    }                                                                          \
} while (0)

__device__ __forceinline__ void ldsm4(uint32_t* r, uint32_t addr) {
    asm volatile("ldmatrix.sync.aligned.m8n8.x4.shared.b16 {%0,%1,%2,%3}, [%4];"
                 : "=r"(r[0]), "=r"(r[1]), "=r"(r[2]), "=r"(r[3]) : "r"(addr));
}

__device__ __forceinline__ void mma16816(float* d, const uint32_t* a,
                                         uint32_t b0, uint32_t b1) {
    asm volatile(
        "mma.sync.aligned.m16n8k16.row.col.f32.f16.f16.f32 "
        "{%0,%1,%2,%3}, {%4,%5,%6,%7}, {%8,%9}, {%0,%1,%2,%3};"
        : "+f"(d[0]), "+f"(d[1]), "+f"(d[2]), "+f"(d[3])
        : "r"(a[0]), "r"(a[1]), "r"(a[2]), "r"(a[3]), "r"(b0), "r"(b1));
}

// Element offset inside the tiled+swizzled operand layout.
__device__ __forceinline__ size_t tileoff(int row, int k, int KT) {
    size_t base = ((size_t)((row >> 7) * KT + (k >> 6))) << 13;
    uint32_t boff = ((uint32_t)(row & 127) << 7) | ((uint32_t)(k & 63) << 1);
    uint32_t sw = boff ^ ((boff >> 3) & 0x70);
    return base + (sw >> 1);
}

__device__ __forceinline__ uint32_t swz(uint32_t boff) {
    return boff ^ ((boff >> 3) & 0x70);
}

// ---------------- bulk-loaded tensor-core GEMM (pure fp16) -------------------
// C = A[M,K] @ B[N,K]^T.  Stage = {A, B} 16 KB tiles (32 KB).
// NSTAGE=3 -> 96 KB/CTA -> 2 CTAs/SM (bubble hiding, proven R13).
// MODE 0: Hout[r*Ncols+c] = fp16(acc + bias[c])   (raw pre-BN activations)
// MODE 1: layer-3 epilogue: +PB/PA[label] table, 2M-row fp32 output layout.
#define TILE16K 16384
#define STG32K  32768
#define NSTAGE  3
#define SMEM_GG (NSTAGE * STG32K + 48)

template <int MODE>
__global__ void __launch_bounds__(256, 2)
k_bulkmma(const __half* __restrict__ Ah_, const __half* __restrict__ Bh_,
          int Mrows, int Ncols, int KT,
          const float* __restrict__ bias, __half* __restrict__ Hout,
          const int* __restrict__ labels, const float* __restrict__ PA,
          const float* __restrict__ PB, float* __restrict__ out) {
    extern __shared__ unsigned char smem[];
    const uint32_t sb = smem_u32(smem);
    const uint32_t mb = sb + NSTAGE * STG32K;   // mbarriers, 8 B apart
    const int tx = threadIdx.x;
    const int lane = tx & 31, wid = tx >> 5;
    const int warpM = wid & 3;           // 4 warps over M (32 rows each)
    const int warpN = wid >> 2;          // 2 warps over N (64 cols each)
    const int rowBase = blockIdx.y * 128;
    const int colBase = blockIdx.x * 128;

    if (tx == 0) {
#pragma unroll
        for (int s = 0; s < NSTAGE; s++) MBAR_INIT(mb + 8 * s, 1);
    }
    __syncthreads();

    const size_t aBase = ((size_t)blockIdx.y * KT) << 13;
    const size_t bBase = ((size_t)blockIdx.x * KT) << 13;

    if (tx == 0) {
        const int pre = (KT < NSTAGE) ? KT : NSTAGE;
        for (int s = 0; s < pre; s++) {
            MBAR_EXPECT(mb + 8 * s, STG32K);
            uint32_t d = sb + (uint32_t)s * STG32K;
            bulkcp(d + 0 * TILE16K, Ah_ + aBase + ((size_t)s << 13), TILE16K, mb + 8 * s);
            bulkcp(d + 1 * TILE16K, Bh_ + bBase + ((size_t)s << 13), TILE16K, mb + 8 * s);
        }
    }

    float acc[2][8][4];
#pragma unroll
    for (int i = 0; i < 2; i++)
#pragma unroll
        for (int j = 0; j < 8; j++)
#pragma unroll
            for (int q = 0; q < 4; q++) acc[i][j][q] = 0.f;

    int ph[NSTAGE] = {0, 0, 0};
    for (int c = 0; c < KT; c++) {
        const int s = c % NSTAGE;
        MBAR_WAIT(mb + 8 * s, ph[s]);
        ph[s] ^= 1;
        const uint32_t stg = sb + (uint32_t)s * STG32K;
#pragma unroll
        for (int ks = 0; ks < 4; ks++) {
            const int k0 = ks * 16;
            uint32_t ah[2][4], bh[4][4];
#pragma unroll
            for (int mf = 0; mf < 2; mf++) {
                uint32_t boff = ((uint32_t)(warpM * 32 + mf * 16 + (lane & 15)) << 7) |
                                ((uint32_t)(k0 + (lane >> 4) * 8) << 1);
                ldsm4(ah[mf], stg + 0 * TILE16K + swz(boff));
            }
            {
                const int grp = lane >> 3, rin = lane & 7;
#pragma unroll
                for (int p = 0; p < 4; p++) {
                    uint32_t boff = ((uint32_t)(warpN * 64 + p * 16 + (grp >> 1) * 8 + rin) << 7) |
                                    ((uint32_t)(k0 + (grp & 1) * 8) << 1);
                    ldsm4(bh[p], stg + 1 * TILE16K + swz(boff));
                }
            }
#pragma unroll
            for (int p = 0; p < 4; p++)
#pragma unroll
                for (int mf = 0; mf < 2; mf++) {
                    mma16816(acc[mf][2 * p + 0], ah[mf], bh[p][0], bh[p][1]);
                    mma16816(acc[mf][2 * p + 1], ah[mf], bh[p][2], bh[p][3]);
                }
        }
        __syncthreads();
        if (c + NSTAGE < KT && tx == 0) {
            const int cn = c + NSTAGE;
            MBAR_EXPECT(mb + 8 * s, STG32K);
            uint32_t d = sb + (uint32_t)s * STG32K;
            bulkcp(d + 0 * TILE16K, Ah_ + aBase + ((size_t)cn << 13), TILE16K, mb + 8 * s);
            bulkcp(d + 1 * TILE16K, Bh_ + bBase + ((size_t)cn << 13), TILE16K, mb + 8 * s);
        }
    }

    // ---------------- epilogue ----------------
#pragma unroll
    for (int mf = 0; mf < 2; mf++) {
#pragma unroll
        for (int half = 0; half < 2; half++) {
            const int r = rowBase + warpM * 32 + mf * 16 + (lane >> 2) + half * 8;
            if (r >= Mrows) continue;
            if (MODE == 0) {
                __half* cp = Hout + (size_t)r * Ncols;
#pragma unroll
                for (int nf = 0; nf < 8; nf++) {
                    const int cc = colBase + warpN * 64 + nf * 8 + (lane & 3) * 2;
                    float2 b = *(const float2*)(bias + cc);
                    __half2 v;
                    v.x = __float2half(acc[mf][nf][half * 2 + 0] + b.x);
                    v.y = __float2half(acc[mf][nf][half * 2 + 1] + b.y);
                    *(__half2*)(cp + cc) = v;
                }
            } else {
                const bool hB = colBase >= 1024;   // Wcat rows >=1024 = WfcB half
                const int lab = labels[r];
                const float* P = hB ? PA : PB;
                const float* pl = P + (size_t)lab * O2;
                float* op = out + ((size_t)r + (hB ? (size_t)MM : 0)) * O2;
                const int cB = (colBase & 1023) + warpN * 64;
#pragma unroll
                for (int nf = 0; nf < 8; nf++) {
                    const int col = cB + nf * 8 + (lane & 3) * 2;
                    float2 p = *(const float2*)(pl + col);
                    float2 v;
                    v.x = acc[mf][nf][half * 2 + 0] + p.x;
                    v.y = acc[mf][nf][half * 2 + 1] + p.y;
                    *(float2*)(op + col) = v;
                }
            }
        }
    }
}

// ---------------- split kernels: fp32 -> tiled swizzled fp16 ----------------
__global__ void k_split_a(const float* __restrict__ src,
                          __half* __restrict__ dst,
                          int rowsSrc, int colsSrc, int K8, int KT,
                          long long total) {
    long long idx = blockIdx.x * (long long)blockDim.x + threadIdx.x;
    if (idx >= total) return;
    int row = (int)(idx / K8);
    int k   = (int)(idx % K8) * 8;
    __half h8[8];
#pragma unroll
    for (int j = 0; j < 8; j++) {
        float v = 0.f;
        if (row < rowsSrc && k + j < colsSrc)
            v = src[(size_t)row * colsSrc + k + j];
        h8[j] = __float2half(v);
    }
    *(uint4*)(dst + tileoff(row, k, KT)) = *(uint4*)h8;
}

// A2 = relu(a1*H1 + c1) from fp16 H1, into tiled fp16
__global__ void k_split_aff_a(const __half* __restrict__ src,
                              const float* __restrict__ aa, const float* __restrict__ cc,
                              __half* __restrict__ dst,
                              int rowsSrc, long long total) {
    long long idx = blockIdx.x * (long long)blockDim.x + threadIdx.x;
    if (idx >= total) return;
    int row = (int)(idx / (HF / 8));
    int k   = (int)(idx % (HF / 8)) * 8;
    __half h8[8];
    if (row < rowsSrc) {
        uint4 raw = *(const uint4*)(src + (size_t)row * HF + k);
        const __half* hp = (const __half*)&raw;
#pragma unroll
        for (int j = 0; j < 8; j++) {
            float v = fmaxf(fmaf(aa[k + j], __half2float(hp[j]), cc[k + j]), 0.f);
            h8[j] = __float2half(v);
        }
    } else {
#pragma unroll
        for (int j = 0; j < 8; j++) h8[j] = __float2half(0.f);
    }
    *(uint4*)(dst + tileoff(row, k, HF / 64)) = *(uint4*)h8;
}

// Wcat[2048,256]: rows 0..1023 = Wfc[:, :256]; rows 1024..2047 = Wfc[:, 256:]
__global__ void k_split_wcat(const float* __restrict__ Wfc,
                             __half* __restrict__ dst) {
    int idx = blockIdx.x * blockDim.x + threadIdx.x;
    if (idx >= 2048 * (HF / 8)) return;
    int o = idx / (HF / 8);
    int k = (idx % (HF / 8)) * 8;
    const float* w = (o < 1024) ? (Wfc + (size_t)o * (2 * HF))
                                : (Wfc + (size_t)(o - 1024) * (2 * HF) + HF);
    __half h8[8];
#pragma unroll
    for (int j = 0; j < 8; j++) h8[j] = __float2half(w[k + j]);
    *(uint4*)(dst + tileoff(o, k, HF / 64)) = *(uint4*)h8;
}

// ---------------- stats / labels / segment mean ------------------------------
__global__ void k_zero(float* s1, float* q1, float* s2, float* q2,
                       float* cfs, int* cnt) {
    int t = blockIdx.x * blockDim.x + threadIdx.x;
    if (t < HF) { s1[t] = 0.f; q1[t] = 0.f; s2[t] = 0.f; q2[t] = 0.f; }
    if (t < KC) cnt[t] = 0;
    if (t < KC * HF) cfs[t] = 0.f;
}

__global__ void k_colstats(const __half* __restrict__ H,
                           float* __restrict__ sum, float* __restrict__ sq) {
    int t = threadIdx.x;
    int per = (NN + gridDim.x - 1) / gridDim.x;
    int r0 = blockIdx.x * per;
    int r1 = min(NN, r0 + per);
    float s = 0.f, q = 0.f;
    for (int r = r0; r < r1; r++) {
        float v = __half2float(H[(size_t)r * HF + t]);
        s += v;
        q = fmaf(v, v, q);
    }
    atomicAdd(&sum[t], s);
    atomicAdd(&sq[t], q);
}

__global__ void k_finalize(const float* __restrict__ sum, const float* __restrict__ sq,
                           const float* __restrict__ gam, const float* __restrict__ bet,
                           float* __restrict__ a, float* __restrict__ c) {
    int t = threadIdx.x;
    const float invN = 1.0f / (float)NN;
    float mean = sum[t] * invN;
    float var  = sq[t] * invN - mean * mean;
    float inv  = rsqrtf(var + EPSV);
    float aa   = gam[t] * inv;
    a[t] = aa;
    c[t] = bet[t] - mean * aa;
}

__global__ void k_labels(const float* __restrict__ cid,
                         int* __restrict__ labels, int* __restrict__ cnt) {
    int m = blockIdx.x * blockDim.x + threadIdx.x;
    if (m >= MM) return;
    const float* row = cid + (size_t)m * KC;
    int best = 0;
    float bv = row[0];
#pragma unroll
    for (int k = 1; k < KC; k++) {
        float v = row[k];
        if (v > bv) { bv = v; best = k; }
    }
    labels[m] = best;
    atomicAdd(&cnt[best], 1);
}

// XC = relu(a2*H2[ci[m]] + c2): fp32 copy (for cluster sums) + tiled fp16
__global__ void k_make_xc(const __half* __restrict__ H2, const int* __restrict__ ci,
                          const float* __restrict__ a2, const float* __restrict__ c2,
                          float* __restrict__ XC, __half* __restrict__ dst) {
    int idx = blockIdx.x * blockDim.x + threadIdx.x;
    if (idx >= MMP * (HF / 8)) return;
    int m = idx / (HF / 8);
    int k = (idx % (HF / 8)) * 8;
    __half h8[8];
    float o8[8];
#pragma unroll
    for (int j = 0; j < 8; j++) o8[j] = 0.f;
    if (m < MM) {
        int r = ci[m];
        uint4 raw = *(const uint4*)(H2 + (size_t)r * HF + k);
        const __half* hp = (const __half*)&raw;
#pragma unroll
        for (int j = 0; j < 8; j++)
            o8[j] = fmaxf(fmaf(a2[k + j], __half2float(hp[j]), c2[k + j]), 0.f);
        float4* xp = (float4*)(XC + (size_t)m * HF + k);
        xp[0] = make_float4(o8[0], o8[1], o8[2], o8[3]);
        xp[1] = make_float4(o8[4], o8[5], o8[6], o8[7]);
    }
#pragma unroll
    for (int j = 0; j < 8; j++) h8[j] = __float2half(o8[j]);
    *(uint4*)(dst + tileoff(m, k, HF / 64)) = *(uint4*)h8;
}

__global__ void k_cluster_accum(const float* __restrict__ XC,
                                const int* __restrict__ labels,
                                float* __restrict__ CFsum) {
    __shared__ float acc[KC * HF];
    int t = threadIdx.x;
    for (int i = t; i < KC * HF; i += blockDim.x) acc[i] = 0.f;
    __syncthreads();
    int per = (MM + gridDim.x - 1) / gridDim.x;
    int m0 = blockIdx.x * per;
    int m1 = min(MM, m0 + per);
    for (int m = m0; m < m1; m++) {
        int lab = labels[m];
        acc[lab * HF + t] += XC[(size_t)m * HF + t];
    }
    __syncthreads();
    for (int i = t; i < KC * HF; i += blockDim.x) atomicAdd(&CFsum[i], acc[i]);
}

__global__ void k_ptab(const float* __restrict__ Wfc, const float* __restrict__ bfc,
                       const float* __restrict__ CFsum, const int* __restrict__ cnt,
                       float* __restrict__ PA, float* __restrict__ PB) {
    __shared__ float cf[HF];
    int k = blockIdx.y;
    int t = threadIdx.x;
    float cnv = (float)cnt[k];
    cf[t] = CFsum[k * HF + t] / cnv;
    __syncthreads();
    int o = blockIdx.x * 256 + t;
    const float* w = Wfc + (size_t)o * (2 * HF);
    float sa = 0.f, sb = 0.f;
#pragma unroll 4
    for (int j = 0; j < HF; j++) {
        float c = cf[j];
        sa = fmaf(c, w[j], sa);
        sb = fmaf(c, w[HF + j], sb);
    }
    float bb = bfc[o];
    PA[k * O2 + o] = sa + bb;
    PB[k * O2 + o] = sb + bb;
}

// ---------------- host launcher ---------------------------------------------
extern "C" void kernel_launch(void* const* d_in, const int* in_sizes, int n_in,
                              void* d_out, int out_size) {
    const float* x    = (const float*)d_in[0];
    const float* cid  = (const float*)d_in[1];
    const int*   cidx = (const int*)  d_in[2];
    const float* W1   = (const float*)d_in[3];
    const float* b1   = (const float*)d_in[4];
    const float* g1   = (const float*)d_in[5];
    const float* be1  = (const float*)d_in[6];
    const float* W2   = (const float*)d_in[7];
    const float* b2   = (const float*)d_in[8];
    const float* g2   = (const float*)d_in[9];
    const float* be2  = (const float*)d_in[10];
    const float* Wfc  = (const float*)d_in[11];
    const float* bfc  = (const float*)d_in[12];
    float* out = (float*)d_out;

    static bool inited = false;
    static float *XC, *sum1, *sq1, *a1, *c1, *sum2, *sq2, *a2, *c2,
                 *CFs, *PA, *PB;
    static int *cnt, *labs;
    static __half *H1, *H2, *xh, *W1h, *A2h, *W2h, *XCh, *WCh;
    if (!inited) {
        inited = true;
        cudaGetSymbolAddress((void**)&H1,   g_H1);
        cudaGetSymbolAddress((void**)&H2,   g_H2);
        cudaGetSymbolAddress((void**)&XC,   g_XC);
        cudaGetSymbolAddress((void**)&sum1, g_sum1);
        cudaGetSymbolAddress((void**)&sq1,  g_sq1);
        cudaGetSymbolAddress((void**)&a1,   g_a1);
        cudaGetSymbolAddress((void**)&c1,   g_c1);
        cudaGetSymbolAddress((void**)&sum2, g_sum2);
        cudaGetSymbolAddress((void**)&sq2,  g_sq2);
        cudaGetSymbolAddress((void**)&a2,   g_a2);
        cudaGetSymbolAddress((void**)&c2,   g_c2);
        cudaGetSymbolAddress((void**)&CFs,  g_CFsum);
        cudaGetSymbolAddress((void**)&PA,   g_PA);
        cudaGetSymbolAddress((void**)&PB,   g_PB);
        cudaGetSymbolAddress((void**)&cnt,  g_counts);
        cudaGetSymbolAddress((void**)&labs, g_labels);
        cudaGetSymbolAddress((void**)&xh,   g_xh);
        cudaGetSymbolAddress((void**)&W1h,  g_W1h);
        cudaGetSymbolAddress((void**)&A2h,  g_A2h);
        cudaGetSymbolAddress((void**)&W2h,  g_W2h);
        cudaGetSymbolAddress((void**)&XCh,  g_XCh);
        cudaGetSymbolAddress((void**)&WCh,  g_WCh);
        cudaFuncSetAttribute(k_bulkmma<0>,
                             cudaFuncAttributeMaxDynamicSharedMemorySize, SMEM_GG);
        cudaFuncSetAttribute(k_bulkmma<1>,
                             cudaFuncAttributeMaxDynamicSharedMemorySize, SMEM_GG);
    }

    // Launch order arranged so the ncu-profiled slot (4th launch) is GEMM1.
    // 0) zero accumulators
    k_zero<<<40, 256>>>(sum1, sq1, sum2, sq2, CFs, cnt);

    // 1) x -> tiled fp16 (rows padded to NNP, K padded to 512)
    {
        long long t = (long long)NNP * (KP1 / 8);
        k_split_a<<<(int)((t + 255) / 256), 256>>>(x, xh,
                                                   NN, D_IN, KP1 / 8, KP1 / 64, t);
    }
    // 2) W1 -> tiled fp16
    {
        long long t1 = (long long)HF * (KP1 / 8);
        k_split_a<<<cdiv_h((int)t1, 256), 256>>>(W1, W1h,
                                                 HF, D_IN, KP1 / 8, KP1 / 64, t1);
    }
    // 3) GEMM1: H1 = fp16(x @ W1^T + b1)        <-- ncu-profiled launch
    {
        dim3 grid(HF / 128, NNP / 128);
        k_bulkmma<0><<<grid, 256, SMEM_GG>>>(xh, W1h,
            NN, HF, KP1 / 64, b1, H1, nullptr, nullptr, nullptr, nullptr);
    }
    // 4) BN1 stats (from fp16 H1)
    k_colstats<<<512, 256>>>(H1, sum1, sq1);
    k_finalize<<<1, 256>>>(sum1, sq1, g1, be1, a1, c1);

    // 5) W2 -> tiled fp16; A2 = relu(a1*H1 + c1); GEMM2
    {
        long long t2 = (long long)HF * (HF / 8);
        k_split_a<<<cdiv_h((int)t2, 256), 256>>>(W2, W2h,
                                                 HF, HF, HF / 8, HF / 64, t2);
        long long t = (long long)NNP * (HF / 8);
        k_split_aff_a<<<(int)((t + 255) / 256), 256>>>(H1, a1, c1, A2h, NN, t);
        dim3 grid(HF / 128, NNP / 128);
        k_bulkmma<0><<<grid, 256, SMEM_GG>>>(A2h, W2h,
            NN, HF, HF / 64, b2, H2, nullptr, nullptr, nullptr, nullptr);
    }
    // 6) BN2 stats
    k_colstats<<<512, 256>>>(H2, sum2, sq2);
    k_finalize<<<1, 256>>>(sum2, sq2, g2, be2, a2, c2);

    // 7) labels + counts
    k_labels<<<cdiv_h(MM, 256), 256>>>(cid, labs, cnt);

    // 8) XC = relu(a2 * H2[cidx] + c2): fp32 + fused fp16 tiling
    k_make_xc<<<cdiv_h(MMP * (HF / 8), 256), 256>>>(H2, cidx, a2, c2, XC, XCh);

    // 9) cluster feature sums (fp32 path)
    k_cluster_accum<<<256, 256>>>(XC, labs, CFs);

    // 10) Wcat -> tiled fp16; PA/PB tables (fp32, exact)
    k_split_wcat<<<cdiv_h(2048 * (HF / 8), 256), 256>>>(Wfc, WCh);
    {
        dim3 grid(O2 / 256, KC);
        k_ptab<<<grid, 256>>>(Wfc, bfc, CFs, cnt, PA, PB);
    }

    // 11) final GEMM: Y = XC @ Wcat^T, epilogue adds PB/PA, scatters rows
    {
        dim3 grid(2048 / 128, MMP / 128);
        k_bulkmma<1><<<grid, 256, SMEM_GG>>>(XCh, WCh,
            MM, 2048, HF / 64, nullptr, nullptr, labs, PA, PB, out);
    }
}

// round 15
// speedup vs baseline: 2.0351x; 1.0321x over previous
#include <cuda_runtime.h>
#include <cuda_fp16.h>
#include <cstdint>

// ---------------- problem constants ----------------------------------------
#define NN   100000   // batch rows
#define NNP  100096   // padded to 128
#define D_IN 500      // input features
#define KP1  512      // D_IN padded to MMA K granularity
#define HF   256      // hidden
#define MM   50000    // cluster rows
#define MMP  50048    // padded to 128
#define KC   40       // clusters
#define O2   1024     // OUT*OUT
#define EPSV 1e-5f

static inline int cdiv_h(int a, int b) { return (a + b - 1) / b; }

// ---------------- device scratch --------------------------------------------
__device__ __half g_H1[(size_t)NN * HF];    // raw GEMM1 out (fp16)
__device__ __half g_H2[(size_t)NN * HF];    // raw GEMM2 out (fp16)
__device__ float g_sum1[HF], g_sq1[HF], g_a1[HF], g_c1[HF];
__device__ float g_sum2[HF], g_sq2[HF], g_a2[HF], g_c2[HF];
__device__ float g_CFsum[KC * HF];
__device__ int   g_counts[KC];
__device__ int   g_labels[MM];
__device__ float g_PA[KC * O2];
__device__ float g_PB[KC * O2];

// Pre-tiled, SW128-swizzled fp16 operands.
// Tile (rowTile, kTile) of 128x64 halfs = 16 KB contiguous; SW128 inside.
__device__ __half g_xh [(size_t)NNP * KP1];
__device__ __half g_W1h[(size_t)HF * KP1];
__device__ __half g_A2h[(size_t)NNP * HF];
__device__ __half g_W2h[(size_t)HF * HF];
__device__ __half g_XCh[(size_t)MMP * HF];
__device__ __half g_WCh[(size_t)2048 * HF];

// ---------------- low-level helpers ------------------------------------------
__device__ __forceinline__ uint32_t smem_u32(const void* p) {
    uint32_t a;
    asm("{ .reg .u64 t; cvta.to.shared.u64 t, %1; cvt.u32.u64 %0, t; }"
        : "=r"(a) : "l"(p));
    return a;
}

__device__ __forceinline__ void bulkcp(uint32_t dst, const void* src,
                                       uint32_t bytes, uint32_t mbar) {
    asm volatile(
        "cp.async.bulk.shared::cluster.global.mbarrier::complete_tx::bytes "
        "[%0], [%1], %2, [%3];"
        :: "r"(dst), "l"(src), "r"(bytes), "r"(mbar) : "memory");
}

#define MBAR_INIT(addr, cnt) \
    asm volatile("mbarrier.init.shared.b64 [%0], %1;" \
                 :: "r"((uint32_t)(addr)), "r"((uint32_t)(cnt)) : "memory")
#define MBAR_EXPECT(addr, tx) \
    asm volatile("mbarrier.arrive.expect_tx.shared.b64 _, [%0], %1;" \
                 :: "r"((uint32_t)(addr)), "r"((uint32_t)(tx)) : "memory")
#define MBAR_WAIT(addr, parity) do {                                           \
    uint32_t _m = (uint32_t)(addr); uint32_t _p = (uint32_t)(parity);          \
    uint32_t _d;                                                               \
    asm volatile("{\n\t.reg .pred p;\n\t"                                      \
        "mbarrier.try_wait.parity.acquire.cta.shared::cta.b64 p, [%1], %2;\n\t"\
        "selp.b32 %0, 1, 0, p;\n\t}" : "=r"(_d) : "r"(_m), "r"(_p) : "memory");\
    if (!_d) {                                                                 \
        asm volatile("{\n\t.reg .pred P1;\n\t"                                 \
            "WL_%=:\n\t"                                                       \
            "mbarrier.try_wait.parity.acquire.cta.shared::cta.b64 P1, [%0], %1, 0x989680;\n\t" \
            "@P1 bra.uni WD_%=;\n\t"                                           \
            "bra.uni WL_%=;\n\t"                                               \
            "WD_%=:\n\t}" :: "r"(_m), "r"(_p) : "memory");                     \
    }                                                                          \
} while (0)

__device__ __forceinline__ void ldsm4(uint32_t* r, uint32_t addr) {
    asm volatile("ldmatrix.sync.aligned.m8n8.x4.shared.b16 {%0,%1,%2,%3}, [%4];"
                 : "=r"(r[0]), "=r"(r[1]), "=r"(r[2]), "=r"(r[3]) : "r"(addr));
}

__device__ __forceinline__ void mma16816(float* d, const uint32_t* a,
                                         uint32_t b0, uint32_t b1) {
    asm volatile(
        "mma.sync.aligned.m16n8k16.row.col.f32.f16.f16.f32 "
        "{%0,%1,%2,%3}, {%4,%5,%6,%7}, {%8,%9}, {%0,%1,%2,%3};"
        : "+f"(d[0]), "+f"(d[1]), "+f"(d[2]), "+f"(d[3])
        : "r"(a[0]), "r"(a[1]), "r"(a[2]), "r"(a[3]), "r"(b0), "r"(b1));
}

// Element offset inside the tiled+swizzled operand layout.
__device__ __forceinline__ size_t tileoff(int row, int k, int KT) {
    size_t base = ((size_t)((row >> 7) * KT + (k >> 6))) << 13;
    uint32_t boff = ((uint32_t)(row & 127) << 7) | ((uint32_t)(k & 63) << 1);
    uint32_t sw = boff ^ ((boff >> 3) & 0x70);
    return base + (sw >> 1);
}

__device__ __forceinline__ uint32_t swz(uint32_t boff) {
    return boff ^ ((boff >> 3) & 0x70);
}

// ---------------- bulk-loaded tensor-core GEMM (pure fp16) -------------------
// C = A[M,K] @ B[N,K]^T.  Stage = {A, B} 16 KB tiles (32 KB).
// NSTAGE=3 -> 96 KB/CTA -> 2 CTAs/SM (bubble hiding, proven R13).
// MODE 0: Hout[r*Ncols+c] = fp16(acc + bias[c])   (raw pre-BN activations)
// MODE 1: layer-3 epilogue: +PB/PA[label] table, 2M-row fp32 output layout.
#define TILE16K 16384
#define STG32K  32768
#define NSTAGE  3
#define SMEM_GG (NSTAGE * STG32K + 48)

template <int MODE>
__global__ void __launch_bounds__(256, 2)
k_bulkmma(const __half* __restrict__ Ah_, const __half* __restrict__ Bh_,
          int Mrows, int Ncols, int KT,
          const float* __restrict__ bias, __half* __restrict__ Hout,
          const int* __restrict__ labels, const float* __restrict__ PA,
          const float* __restrict__ PB, float* __restrict__ out) {
    extern __shared__ unsigned char smem[];
    const uint32_t sb = smem_u32(smem);
    const uint32_t mb = sb + NSTAGE * STG32K;   // mbarriers, 8 B apart
    const int tx = threadIdx.x;
    const int lane = tx & 31, wid = tx >> 5;
    const int warpM = wid & 3;           // 4 warps over M (32 rows each)
    const int warpN = wid >> 2;          // 2 warps over N (64 cols each)
    const int rowBase = blockIdx.y * 128;
    const int colBase = blockIdx.x * 128;

    if (tx == 0) {
#pragma unroll
        for (int s = 0; s < NSTAGE; s++) MBAR_INIT(mb + 8 * s, 1);
    }
    __syncthreads();

    const size_t aBase = ((size_t)blockIdx.y * KT) << 13;
    const size_t bBase = ((size_t)blockIdx.x * KT) << 13;

    if (tx == 0) {
        const int pre = (KT < NSTAGE) ? KT : NSTAGE;
        for (int s = 0; s < pre; s++) {
            MBAR_EXPECT(mb + 8 * s, STG32K);
            uint32_t d = sb + (uint32_t)s * STG32K;
            bulkcp(d + 0 * TILE16K, Ah_ + aBase + ((size_t)s << 13), TILE16K, mb + 8 * s);
            bulkcp(d + 1 * TILE16K, Bh_ + bBase + ((size_t)s << 13), TILE16K, mb + 8 * s);
        }
    }

    float acc[2][8][4];
#pragma unroll
    for (int i = 0; i < 2; i++)
#pragma unroll
        for (int j = 0; j < 8; j++)
#pragma unroll
            for (int q = 0; q < 4; q++) acc[i][j][q] = 0.f;

    int ph[NSTAGE] = {0, 0, 0};
    for (int c = 0; c < KT; c++) {
        const int s = c % NSTAGE;
        MBAR_WAIT(mb + 8 * s, ph[s]);
        ph[s] ^= 1;
        const uint32_t stg = sb + (uint32_t)s * STG32K;
#pragma unroll
        for (int ks = 0; ks < 4; ks++) {
            const int k0 = ks * 16;
            uint32_t ah[2][4], bh[4][4];
#pragma unroll
            for (int mf = 0; mf < 2; mf++) {
                uint32_t boff = ((uint32_t)(warpM * 32 + mf * 16 + (lane & 15)) << 7) |
                                ((uint32_t)(k0 + (lane >> 4) * 8) << 1);
                ldsm4(ah[mf], stg + 0 * TILE16K + swz(boff));
            }
            {
                const int grp = lane >> 3, rin = lane & 7;
#pragma unroll
                for (int p = 0; p < 4; p++) {
                    uint32_t boff = ((uint32_t)(warpN * 64 + p * 16 + (grp >> 1) * 8 + rin) << 7) |
                                    ((uint32_t)(k0 + (grp & 1) * 8) << 1);
                    ldsm4(bh[p], stg + 1 * TILE16K + swz(boff));
                }
            }
#pragma unroll
            for (int p = 0; p < 4; p++)
#pragma unroll
                for (int mf = 0; mf < 2; mf++) {
                    mma16816(acc[mf][2 * p + 0], ah[mf], bh[p][0], bh[p][1]);
                    mma16816(acc[mf][2 * p + 1], ah[mf], bh[p][2], bh[p][3]);
                }
        }
        __syncthreads();
        if (c + NSTAGE < KT && tx == 0) {
            const int cn = c + NSTAGE;
            MBAR_EXPECT(mb + 8 * s, STG32K);
            uint32_t d = sb + (uint32_t)s * STG32K;
            bulkcp(d + 0 * TILE16K, Ah_ + aBase + ((size_t)cn << 13), TILE16K, mb + 8 * s);
            bulkcp(d + 1 * TILE16K, Bh_ + bBase + ((size_t)cn << 13), TILE16K, mb + 8 * s);
        }
    }

    // ---------------- epilogue ----------------
#pragma unroll
    for (int mf = 0; mf < 2; mf++) {
#pragma unroll
        for (int half = 0; half < 2; half++) {
            const int r = rowBase + warpM * 32 + mf * 16 + (lane >> 2) + half * 8;
            if (r >= Mrows) continue;
            if (MODE == 0) {
                __half* cp = Hout + (size_t)r * Ncols;
#pragma unroll
                for (int nf = 0; nf < 8; nf++) {
                    const int cc = colBase + warpN * 64 + nf * 8 + (lane & 3) * 2;
                    float2 b = *(const float2*)(bias + cc);
                    __half2 v;
                    v.x = __float2half(acc[mf][nf][half * 2 + 0] + b.x);
                    v.y = __float2half(acc[mf][nf][half * 2 + 1] + b.y);
                    *(__half2*)(cp + cc) = v;
                }
            } else {
                const bool hB = colBase >= 1024;   // Wcat rows >=1024 = WfcB half
                const int lab = labels[r];
                const float* P = hB ? PA : PB;
                const float* pl = P + (size_t)lab * O2;
                float* op = out + ((size_t)r + (hB ? (size_t)MM : 0)) * O2;
                const int cB = (colBase & 1023) + warpN * 64;
#pragma unroll
                for (int nf = 0; nf < 8; nf++) {
                    const int col = cB + nf * 8 + (lane & 3) * 2;
                    float2 p = *(const float2*)(pl + col);
                    float2 v;
                    v.x = acc[mf][nf][half * 2 + 0] + p.x;
                    v.y = acc[mf][nf][half * 2 + 1] + p.y;
                    *(float2*)(op + col) = v;
                }
            }
        }
    }
}

// ---------------- split kernels: fp32 -> tiled swizzled fp16 ----------------
// Vectorized: rows of all sources are 16B-aligned (x: 500*4=2000 B = 125*16;
// W2: 1024 B; Wcat: 2048 B), and k is a multiple of 8 -> the 8-float group is
// two aligned float4 loads whenever it fits entirely inside the row.
__global__ void k_split_a(const float* __restrict__ src,
                          __half* __restrict__ dst,
                          int rowsSrc, int colsSrc, int K8, int KT,
                          long long total) {
    long long idx = blockIdx.x * (long long)blockDim.x + threadIdx.x;
    if (idx >= total) return;
    int row = (int)(idx / K8);
    int k   = (int)(idx % K8) * 8;
    __half h8[8];
    if (row < rowsSrc && k + 8 <= colsSrc) {
        const float4* sp = (const float4*)(src + (size_t)row * colsSrc + k);
        float4 v0 = sp[0], v1 = sp[1];
        h8[0] = __float2half(v0.x); h8[1] = __float2half(v0.y);
        h8[2] = __float2half(v0.z); h8[3] = __float2half(v0.w);
        h8[4] = __float2half(v1.x); h8[5] = __float2half(v1.y);
        h8[6] = __float2half(v1.z); h8[7] = __float2half(v1.w);
    } else {
#pragma unroll
        for (int j = 0; j < 8; j++) {
            float v = 0.f;
            if (row < rowsSrc && k + j < colsSrc)
                v = src[(size_t)row * colsSrc + k + j];
            h8[j] = __float2half(v);
        }
    }
    *(uint4*)(dst + tileoff(row, k, KT)) = *(uint4*)h8;
}

// A2 = relu(a1*H1 + c1) from fp16 H1, into tiled fp16
__global__ void k_split_aff_a(const __half* __restrict__ src,
                              const float* __restrict__ aa, const float* __restrict__ cc,
                              __half* __restrict__ dst,
                              int rowsSrc, long long total) {
    long long idx = blockIdx.x * (long long)blockDim.x + threadIdx.x;
    if (idx >= total) return;
    int row = (int)(idx / (HF / 8));
    int k   = (int)(idx % (HF / 8)) * 8;
    __half h8[8];
    if (row < rowsSrc) {
        uint4 raw = *(const uint4*)(src + (size_t)row * HF + k);
        const __half* hp = (const __half*)&raw;
#pragma unroll
        for (int j = 0; j < 8; j++) {
            float v = fmaxf(fmaf(aa[k + j], __half2float(hp[j]), cc[k + j]), 0.f);
            h8[j] = __float2half(v);
        }
    } else {
#pragma unroll
        for (int j = 0; j < 8; j++) h8[j] = __float2half(0.f);
    }
    *(uint4*)(dst + tileoff(row, k, HF / 64)) = *(uint4*)h8;
}

// Wcat[2048,256]: rows 0..1023 = Wfc[:, :256]; rows 1024..2047 = Wfc[:, 256:]
__global__ void k_split_wcat(const float* __restrict__ Wfc,
                             __half* __restrict__ dst) {
    int idx = blockIdx.x * blockDim.x + threadIdx.x;
    if (idx >= 2048 * (HF / 8)) return;
    int o = idx / (HF / 8);
    int k = (idx % (HF / 8)) * 8;
    const float* w = (o < 1024) ? (Wfc + (size_t)o * (2 * HF))
                                : (Wfc + (size_t)(o - 1024) * (2 * HF) + HF);
    const float4* sp = (const float4*)(w + k);
    float4 v0 = sp[0], v1 = sp[1];
    __half h8[8];
    h8[0] = __float2half(v0.x); h8[1] = __float2half(v0.y);
    h8[2] = __float2half(v0.z); h8[3] = __float2half(v0.w);
    h8[4] = __float2half(v1.x); h8[5] = __float2half(v1.y);
    h8[6] = __float2half(v1.z); h8[7] = __float2half(v1.w);
    *(uint4*)(dst + tileoff(o, k, HF / 64)) = *(uint4*)h8;
}

// ---------------- stats / labels ---------------------------------------------
__global__ void k_zero(float* s1, float* q1, float* s2, float* q2,
                       float* cfs, int* cnt) {
    int t = blockIdx.x * blockDim.x + threadIdx.x;
    if (t < HF) { s1[t] = 0.f; q1[t] = 0.f; s2[t] = 0.f; q2[t] = 0.f; }
    if (t < KC) cnt[t] = 0;
    if (t < KC * HF) cfs[t] = 0.f;
}

__global__ void k_colstats(const __half* __restrict__ H,
                           float* __restrict__ sum, float* __restrict__ sq) {
    int t = threadIdx.x;
    int per = (NN + gridDim.x - 1) / gridDim.x;
    int r0 = blockIdx.x * per;
    int r1 = min(NN, r0 + per);
    float s = 0.f, q = 0.f;
    for (int r = r0; r < r1; r++) {
        float v = __half2float(H[(size_t)r * HF + t]);
        s += v;
        q = fmaf(v, v, q);
    }
    atomicAdd(&sum[t], s);
    atomicAdd(&sq[t], q);
}

__global__ void k_finalize(const float* __restrict__ sum, const float* __restrict__ sq,
                           const float* __restrict__ gam, const float* __restrict__ bet,
                           float* __restrict__ a, float* __restrict__ c) {
    int t = threadIdx.x;
    const float invN = 1.0f / (float)NN;
    float mean = sum[t] * invN;
    float var  = sq[t] * invN - mean * mean;
    float inv  = rsqrtf(var + EPSV);
    float aa   = gam[t] * inv;
    a[t] = aa;
    c[t] = bet[t] - mean * aa;
}

__global__ void k_labels(const float* __restrict__ cid,
                         int* __restrict__ labels, int* __restrict__ cnt) {
    int m = blockIdx.x * blockDim.x + threadIdx.x;
    if (m >= MM) return;
    const float* row = cid + (size_t)m * KC;
    int best = 0;
    float bv = row[0];
#pragma unroll
    for (int k = 1; k < KC; k++) {
        float v = row[k];
        if (v > bv) { bv = v; best = k; }
    }
    labels[m] = best;
    atomicAdd(&cnt[best], 1);
}

// ---------------- fused XC pipeline ------------------------------------------
// One kernel replaces make_xc + cluster_accum and removes the fp32 XC buffer:
// v = relu(a2*H2[ci[m]][t] + c2[t]); XCh[tiled(m,t)] = fp16(v);
// acc[lab[m]*HF + t] += v  (smem), then one atomicAdd pass into CFsum.
// Same 256-block / serial-row structure as the old cluster_accum -> identical
// summation order -> bit-identical CFsum.
__global__ void k_xc_fused(const __half* __restrict__ H2,
                           const int* __restrict__ ci,
                           const int* __restrict__ labels,
                           const float* __restrict__ a2,
                           const float* __restrict__ c2,
                           __half* __restrict__ XCh,
                           float* __restrict__ CFsum) {
    __shared__ float acc[KC * HF];   // 40 KB
    const int t = threadIdx.x;
    for (int i = t; i < KC * HF; i += 256) acc[i] = 0.f;
    __syncthreads();
    const float av = a2[t], cv = c2[t];
    const int per = (MMP + gridDim.x - 1) / gridDim.x;
    const int m0 = blockIdx.x * per;
    const int m1 = min(MMP, m0 + per);
    for (int m = m0; m < m1; m++) {
        float v = 0.f;
        if (m < MM) {
            const int r = ci[m];
            v = fmaxf(fmaf(av, __half2float(H2[(size_t)r * HF + t]), cv), 0.f);
            acc[labels[m] * HF + t] += v;
        }
        XCh[tileoff(m, t, HF / 64)] = __float2half(v);
    }
    __syncthreads();
    for (int i = t; i < KC * HF; i += 256) atomicAdd(&CFsum[i], acc[i]);
}

__global__ void k_ptab(const float* __restrict__ Wfc, const float* __restrict__ bfc,
                       const float* __restrict__ CFsum, const int* __restrict__ cnt,
                       float* __restrict__ PA, float* __restrict__ PB) {
    __shared__ float cf[HF];
    int k = blockIdx.y;
    int t = threadIdx.x;
    float cnv = (float)cnt[k];
    cf[t] = CFsum[k * HF + t] / cnv;
    __syncthreads();
    int o = blockIdx.x * 256 + t;
    const float* w = Wfc + (size_t)o * (2 * HF);
    float sa = 0.f, sb = 0.f;
#pragma unroll 4
    for (int j = 0; j < HF; j++) {
        float c = cf[j];
        sa = fmaf(c, w[j], sa);
        sb = fmaf(c, w[HF + j], sb);
    }
    float bb = bfc[o];
    PA[k * O2 + o] = sa + bb;
    PB[k * O2 + o] = sb + bb;
}

// ---------------- host launcher ---------------------------------------------
extern "C" void kernel_launch(void* const* d_in, const int* in_sizes, int n_in,
                              void* d_out, int out_size) {
    const float* x    = (const float*)d_in[0];
    const float* cid  = (const float*)d_in[1];
    const int*   cidx = (const int*)  d_in[2];
    const float* W1   = (const float*)d_in[3];
    const float* b1   = (const float*)d_in[4];
    const float* g1   = (const float*)d_in[5];
    const float* be1  = (const float*)d_in[6];
    const float* W2   = (const float*)d_in[7];
    const float* b2   = (const float*)d_in[8];
    const float* g2   = (const float*)d_in[9];
    const float* be2  = (const float*)d_in[10];
    const float* Wfc  = (const float*)d_in[11];
    const float* bfc  = (const float*)d_in[12];
    float* out = (float*)d_out;

    static bool inited = false;
    static float *sum1, *sq1, *a1, *c1, *sum2, *sq2, *a2, *c2, *CFs, *PA, *PB;
    static int *cnt, *labs;
    static __half *H1, *H2, *xh, *W1h, *A2h, *W2h, *XCh, *WCh;
    if (!inited) {
        inited = true;
        cudaGetSymbolAddress((void**)&H1,   g_H1);
        cudaGetSymbolAddress((void**)&H2,   g_H2);
        cudaGetSymbolAddress((void**)&sum1, g_sum1);
        cudaGetSymbolAddress((void**)&sq1,  g_sq1);
        cudaGetSymbolAddress((void**)&a1,   g_a1);
        cudaGetSymbolAddress((void**)&c1,   g_c1);
        cudaGetSymbolAddress((void**)&sum2, g_sum2);
        cudaGetSymbolAddress((void**)&sq2,  g_sq2);
        cudaGetSymbolAddress((void**)&a2,   g_a2);
        cudaGetSymbolAddress((void**)&c2,   g_c2);
        cudaGetSymbolAddress((void**)&CFs,  g_CFsum);
        cudaGetSymbolAddress((void**)&PA,   g_PA);
        cudaGetSymbolAddress((void**)&PB,   g_PB);
        cudaGetSymbolAddress((void**)&cnt,  g_counts);
        cudaGetSymbolAddress((void**)&labs, g_labels);
        cudaGetSymbolAddress((void**)&xh,   g_xh);
        cudaGetSymbolAddress((void**)&W1h,  g_W1h);
        cudaGetSymbolAddress((void**)&A2h,  g_A2h);
        cudaGetSymbolAddress((void**)&W2h,  g_W2h);
        cudaGetSymbolAddress((void**)&XCh,  g_XCh);
        cudaGetSymbolAddress((void**)&WCh,  g_WCh);
        cudaFuncSetAttribute(k_bulkmma<0>,
                             cudaFuncAttributeMaxDynamicSharedMemorySize, SMEM_GG);
        cudaFuncSetAttribute(k_bulkmma<1>,
                             cudaFuncAttributeMaxDynamicSharedMemorySize, SMEM_GG);
    }

    // Launch order keeps GEMM1 in the ncu-profiled slot (4th launch).
    // 0) zero accumulators
    k_zero<<<40, 256>>>(sum1, sq1, sum2, sq2, CFs, cnt);

    // 1) x -> tiled fp16 (rows padded to NNP, K padded to 512)
    {
        long long t = (long long)NNP * (KP1 / 8);
        k_split_a<<<(int)((t + 255) / 256), 256>>>(x, xh,
                                                   NN, D_IN, KP1 / 8, KP1 / 64, t);
    }
    // 2) W1 -> tiled fp16
    {
        long long t1 = (long long)HF * (KP1 / 8);
        k_split_a<<<cdiv_h((int)t1, 256), 256>>>(W1, W1h,
                                                 HF, D_IN, KP1 / 8, KP1 / 64, t1);
    }
    // 3) GEMM1: H1 = fp16(x @ W1^T + b1)        <-- ncu-profiled launch
    {
        dim3 grid(HF / 128, NNP / 128);
        k_bulkmma<0><<<grid, 256, SMEM_GG>>>(xh, W1h,
            NN, HF, KP1 / 64, b1, H1, nullptr, nullptr, nullptr, nullptr);
    }
    // 4) BN1 stats (from fp16 H1)
    k_colstats<<<512, 256>>>(H1, sum1, sq1);
    k_finalize<<<1, 256>>>(sum1, sq1, g1, be1, a1, c1);

    // 5) W2 -> tiled fp16; A2 = relu(a1*H1 + c1); GEMM2
    {
        long long t2 = (long long)HF * (HF / 8);
        k_split_a<<<cdiv_h((int)t2, 256), 256>>>(W2, W2h,
                                                 HF, HF, HF / 8, HF / 64, t2);
        long long t = (long long)NNP * (HF / 8);
        k_split_aff_a<<<(int)((t + 255) / 256), 256>>>(H1, a1, c1, A2h, NN, t);
        dim3 grid(HF / 128, NNP / 128);
        k_bulkmma<0><<<grid, 256, SMEM_GG>>>(A2h, W2h,
            NN, HF, HF / 64, b2, H2, nullptr, nullptr, nullptr, nullptr);
    }
    // 6) BN2 stats
    k_colstats<<<512, 256>>>(H2, sum2, sq2);
    k_finalize<<<1, 256>>>(sum2, sq2, g2, be2, a2, c2);

    // 7) labels + counts
    k_labels<<<cdiv_h(MM, 256), 256>>>(cid, labs, cnt);

    // 8) fused: XCh (tiled fp16) + cluster feature sums, no fp32 XC buffer
    k_xc_fused<<<256, 256>>>(H2, cidx, labs, a2, c2, XCh, CFs);

    // 9) Wcat -> tiled fp16; PA/PB tables (fp32, exact)
    k_split_wcat<<<cdiv_h(2048 * (HF / 8), 256), 256>>>(Wfc, WCh);
    {
        dim3 grid(O2 / 256, KC);
        k_ptab<<<grid, 256>>>(Wfc, bfc, CFs, cnt, PA, PB);
    }

    // 10) final GEMM: Y = XC @ Wcat^T, epilogue adds PB/PA, scatters rows
    {
        dim3 grid(2048 / 128, MMP / 128);
        k_bulkmma<1><<<grid, 256, SMEM_GG>>>(XCh, WCh,
            MM, 2048, HF / 64, nullptr, nullptr, labs, PA, PB, out);
    }
}

// round 16
// speedup vs baseline: 2.0540x; 1.0093x over previous
#include <cuda_runtime.h>
#include <cuda_fp16.h>
#include <cstdint>

// ---------------- problem constants ----------------------------------------
#define NN   100000   // batch rows
#define NNP  100096   // padded to 128
#define D_IN 500      // input features
#define KP1  512      // D_IN padded to MMA K granularity
#define HF   256      // hidden
#define MM   50000    // cluster rows
#define MMP  50048    // padded to 128
#define KC   40       // clusters
#define O2   1024     // OUT*OUT
#define EPSV 1e-5f

static inline int cdiv_h(int a, int b) { return (a + b - 1) / b; }

// ---------------- device scratch --------------------------------------------
__device__ __half g_H1[(size_t)NN * HF];    // raw GEMM1 out (fp16)
__device__ __half g_H2[(size_t)NN * HF];    // raw GEMM2 out (fp16)
__device__ float g_sum1[HF], g_sq1[HF], g_a1[HF], g_c1[HF];
__device__ float g_sum2[HF], g_sq2[HF], g_a2[HF], g_c2[HF];
__device__ float g_CFsum[KC * HF];
__device__ int   g_counts[KC];
__device__ int   g_labels[MM];
__device__ float g_PA[KC * O2];
__device__ float g_PB[KC * O2];

// Pre-tiled, SW128-swizzled fp16 operands.
// Tile (rowTile, kTile) of 128x64 halfs = 16 KB contiguous; SW128 inside.
__device__ __half g_xh [(size_t)NNP * KP1];
__device__ __half g_W1h[(size_t)HF * KP1];
__device__ __half g_A2h[(size_t)NNP * HF];
__device__ __half g_W2h[(size_t)HF * HF];
__device__ __half g_XCh[(size_t)MMP * HF];
__device__ __half g_WCh[(size_t)2048 * HF];

// ---------------- low-level helpers ------------------------------------------
__device__ __forceinline__ uint32_t smem_u32(const void* p) {
    uint32_t a;
    asm("{ .reg .u64 t; cvta.to.shared.u64 t, %1; cvt.u32.u64 %0, t; }"
        : "=r"(a) : "l"(p));
    return a;
}

__device__ __forceinline__ void bulkcp(uint32_t dst, const void* src,
                                       uint32_t bytes, uint32_t mbar) {
    asm volatile(
        "cp.async.bulk.shared::cluster.global.mbarrier::complete_tx::bytes "
        "[%0], [%1], %2, [%3];"
        :: "r"(dst), "l"(src), "r"(bytes), "r"(mbar) : "memory");
}

#define MBAR_INIT(addr, cnt) \
    asm volatile("mbarrier.init.shared.b64 [%0], %1;" \
                 :: "r"((uint32_t)(addr)), "r"((uint32_t)(cnt)) : "memory")
#define MBAR_EXPECT(addr, tx) \
    asm volatile("mbarrier.arrive.expect_tx.shared.b64 _, [%0], %1;" \
                 :: "r"((uint32_t)(addr)), "r"((uint32_t)(tx)) : "memory")
#define MBAR_WAIT(addr, parity) do {                                           \
    uint32_t _m = (uint32_t)(addr); uint32_t _p = (uint32_t)(parity);          \
    uint32_t _d;                                                               \
    asm volatile("{\n\t.reg .pred p;\n\t"                                      \
        "mbarrier.try_wait.parity.acquire.cta.shared::cta.b64 p, [%1], %2;\n\t"\
        "selp.b32 %0, 1, 0, p;\n\t}" : "=r"(_d) : "r"(_m), "r"(_p) : "memory");\
    if (!_d) {                                                                 \
        asm volatile("{\n\t.reg .pred P1;\n\t"                                 \
            "WL_%=:\n\t"                                                       \
            "mbarrier.try_wait.parity.acquire.cta.shared::cta.b64 P1, [%0], %1, 0x989680;\n\t" \
            "@P1 bra.uni WD_%=;\n\t"                                           \
            "bra.uni WL_%=;\n\t"                                               \
            "WD_%=:\n\t}" :: "r"(_m), "r"(_p) : "memory");                     \
    }                                                                          \
} while (0)

__device__ __forceinline__ void ldsm4(uint32_t* r, uint32_t addr) {
    asm volatile("ldmatrix.sync.aligned.m8n8.x4.shared.b16 {%0,%1,%2,%3}, [%4];"
                 : "=r"(r[0]), "=r"(r[1]), "=r"(r[2]), "=r"(r[3]) : "r"(addr));
}

__device__ __forceinline__ void mma16816(float* d, const uint32_t* a,
                                         uint32_t b0, uint32_t b1) {
    asm volatile(
        "mma.sync.aligned.m16n8k16.row.col.f32.f16.f16.f32 "
        "{%0,%1,%2,%3}, {%4,%5,%6,%7}, {%8,%9}, {%0,%1,%2,%3};"
        : "+f"(d[0]), "+f"(d[1]), "+f"(d[2]), "+f"(d[3])
        : "r"(a[0]), "r"(a[1]), "r"(a[2]), "r"(a[3]), "r"(b0), "r"(b1));
}

// Element offset inside the tiled+swizzled operand layout.
__device__ __forceinline__ size_t tileoff(int row, int k, int KT) {
    size_t base = ((size_t)((row >> 7) * KT + (k >> 6))) << 13;
    uint32_t boff = ((uint32_t)(row & 127) << 7) | ((uint32_t)(k & 63) << 1);
    uint32_t sw = boff ^ ((boff >> 3) & 0x70);
    return base + (sw >> 1);
}

__device__ __forceinline__ uint32_t swz(uint32_t boff) {
    return boff ^ ((boff >> 3) & 0x70);
}

// ---------------- bulk-loaded tensor-core GEMM (pure fp16) -------------------
// C = A[M,K] @ B[N,K]^T.  Stage = {A, B} 16 KB tiles (32 KB).
// NSTAGE=3 -> 96 KB/CTA -> 2 CTAs/SM (bubble hiding, proven R13).
// MODE 0: Hout[r*Ncols+c] = fp16(acc + bias[c])   (raw pre-BN activations)
// MODE 1: layer-3 epilogue: +PB/PA[label] table, 2M-row fp32 output layout.
#define TILE16K 16384
#define STG32K  32768
#define NSTAGE  3
#define SMEM_GG (NSTAGE * STG32K + 48)

template <int MODE>
__global__ void __launch_bounds__(256, 2)
k_bulkmma(const __half* __restrict__ Ah_, const __half* __restrict__ Bh_,
          int Mrows, int Ncols, int KT,
          const float* __restrict__ bias, __half* __restrict__ Hout,
          const int* __restrict__ labels, const float* __restrict__ PA,
          const float* __restrict__ PB, float* __restrict__ out) {
    extern __shared__ unsigned char smem[];
    const uint32_t sb = smem_u32(smem);
    const uint32_t mb = sb + NSTAGE * STG32K;   // mbarriers, 8 B apart
    const int tx = threadIdx.x;
    const int lane = tx & 31, wid = tx >> 5;
    const int warpM = wid & 3;           // 4 warps over M (32 rows each)
    const int warpN = wid >> 2;          // 2 warps over N (64 cols each)
    const int rowBase = blockIdx.y * 128;
    const int colBase = blockIdx.x * 128;

    if (tx == 0) {
#pragma unroll
        for (int s = 0; s < NSTAGE; s++) MBAR_INIT(mb + 8 * s, 1);
    }
    __syncthreads();

    const size_t aBase = ((size_t)blockIdx.y * KT) << 13;
    const size_t bBase = ((size_t)blockIdx.x * KT) << 13;

    if (tx == 0) {
        const int pre = (KT < NSTAGE) ? KT : NSTAGE;
        for (int s = 0; s < pre; s++) {
            MBAR_EXPECT(mb + 8 * s, STG32K);
            uint32_t d = sb + (uint32_t)s * STG32K;
            bulkcp(d + 0 * TILE16K, Ah_ + aBase + ((size_t)s << 13), TILE16K, mb + 8 * s);
            bulkcp(d + 1 * TILE16K, Bh_ + bBase + ((size_t)s << 13), TILE16K, mb + 8 * s);
        }
    }

    float acc[2][8][4];
#pragma unroll
    for (int i = 0; i < 2; i++)
#pragma unroll
        for (int j = 0; j < 8; j++)
#pragma unroll
            for (int q = 0; q < 4; q++) acc[i][j][q] = 0.f;

    int ph[NSTAGE] = {0, 0, 0};
    for (int c = 0; c < KT; c++) {
        const int s = c % NSTAGE;
        MBAR_WAIT(mb + 8 * s, ph[s]);
        ph[s] ^= 1;
        const uint32_t stg = sb + (uint32_t)s * STG32K;
#pragma unroll
        for (int ks = 0; ks < 4; ks++) {
            const int k0 = ks * 16;
            uint32_t ah[2][4], bh[4][4];
#pragma unroll
            for (int mf = 0; mf < 2; mf++) {
                uint32_t boff = ((uint32_t)(warpM * 32 + mf * 16 + (lane & 15)) << 7) |
                                ((uint32_t)(k0 + (lane >> 4) * 8) << 1);
                ldsm4(ah[mf], stg + 0 * TILE16K + swz(boff));
            }
            {
                const int grp = lane >> 3, rin = lane & 7;
#pragma unroll
                for (int p = 0; p < 4; p++) {
                    uint32_t boff = ((uint32_t)(warpN * 64 + p * 16 + (grp >> 1) * 8 + rin) << 7) |
                                    ((uint32_t)(k0 + (grp & 1) * 8) << 1);
                    ldsm4(bh[p], stg + 1 * TILE16K + swz(boff));
                }
            }
#pragma unroll
            for (int p = 0; p < 4; p++)
#pragma unroll
                for (int mf = 0; mf < 2; mf++) {
                    mma16816(acc[mf][2 * p + 0], ah[mf], bh[p][0], bh[p][1]);
                    mma16816(acc[mf][2 * p + 1], ah[mf], bh[p][2], bh[p][3]);
                }
        }
        __syncthreads();
        if (c + NSTAGE < KT && tx == 0) {
            const int cn = c + NSTAGE;
            MBAR_EXPECT(mb + 8 * s, STG32K);
            uint32_t d = sb + (uint32_t)s * STG32K;
            bulkcp(d + 0 * TILE16K, Ah_ + aBase + ((size_t)cn << 13), TILE16K, mb + 8 * s);
            bulkcp(d + 1 * TILE16K, Bh_ + bBase + ((size_t)cn << 13), TILE16K, mb + 8 * s);
        }
    }

    // ---------------- epilogue ----------------
#pragma unroll
    for (int mf = 0; mf < 2; mf++) {
#pragma unroll
        for (int half = 0; half < 2; half++) {
            const int r = rowBase + warpM * 32 + mf * 16 + (lane >> 2) + half * 8;
            if (r >= Mrows) continue;
            if (MODE == 0) {
                __half* cp = Hout + (size_t)r * Ncols;
#pragma unroll
                for (int nf = 0; nf < 8; nf++) {
                    const int cc = colBase + warpN * 64 + nf * 8 + (lane & 3) * 2;
                    float2 b = *(const float2*)(bias + cc);
                    __half2 v;
                    v.x = __float2half(acc[mf][nf][half * 2 + 0] + b.x);
                    v.y = __float2half(acc[mf][nf][half * 2 + 1] + b.y);
                    *(__half2*)(cp + cc) = v;
                }
            } else {
                const bool hB = colBase >= 1024;   // Wcat rows >=1024 = WfcB half
                const int lab = labels[r];
                const float* P = hB ? PA : PB;
                const float* pl = P + (size_t)lab * O2;
                float* op = out + ((size_t)r + (hB ? (size_t)MM : 0)) * O2;
                const int cB = (colBase & 1023) + warpN * 64;
#pragma unroll
                for (int nf = 0; nf < 8; nf++) {
                    const int col = cB + nf * 8 + (lane & 3) * 2;
                    float2 p = *(const float2*)(pl + col);
                    float2 v;
                    v.x = acc[mf][nf][half * 2 + 0] + p.x;
                    v.y = acc[mf][nf][half * 2 + 1] + p.y;
                    *(float2*)(op + col) = v;
                }
            }
        }
    }
}

// ---------------- split kernels: fp32 -> tiled swizzled fp16 ----------------
__global__ void k_split_a(const float* __restrict__ src,
                          __half* __restrict__ dst,
                          int rowsSrc, int colsSrc, int K8, int KT,
                          long long total) {
    long long idx = blockIdx.x * (long long)blockDim.x + threadIdx.x;
    if (idx >= total) return;
    int row = (int)(idx / K8);
    int k   = (int)(idx % K8) * 8;
    __half h8[8];
    if (row < rowsSrc && k + 8 <= colsSrc) {
        const float4* sp = (const float4*)(src + (size_t)row * colsSrc + k);
        float4 v0 = sp[0], v1 = sp[1];
        h8[0] = __float2half(v0.x); h8[1] = __float2half(v0.y);
        h8[2] = __float2half(v0.z); h8[3] = __float2half(v0.w);
        h8[4] = __float2half(v1.x); h8[5] = __float2half(v1.y);
        h8[6] = __float2half(v1.z); h8[7] = __float2half(v1.w);
    } else {
#pragma unroll
        for (int j = 0; j < 8; j++) {
            float v = 0.f;
            if (row < rowsSrc && k + j < colsSrc)
                v = src[(size_t)row * colsSrc + k + j];
            h8[j] = __float2half(v);
        }
    }
    *(uint4*)(dst + tileoff(row, k, KT)) = *(uint4*)h8;
}

// A2 = relu(a1*H1 + c1) from fp16 H1, into tiled fp16
__global__ void k_split_aff_a(const __half* __restrict__ src,
                              const float* __restrict__ aa, const float* __restrict__ cc,
                              __half* __restrict__ dst,
                              int rowsSrc, long long total) {
    long long idx = blockIdx.x * (long long)blockDim.x + threadIdx.x;
    if (idx >= total) return;
    int row = (int)(idx / (HF / 8));
    int k   = (int)(idx % (HF / 8)) * 8;
    __half h8[8];
    if (row < rowsSrc) {
        uint4 raw = *(const uint4*)(src + (size_t)row * HF + k);
        const __half* hp = (const __half*)&raw;
#pragma unroll
        for (int j = 0; j < 8; j++) {
            float v = fmaxf(fmaf(aa[k + j], __half2float(hp[j]), cc[k + j]), 0.f);
            h8[j] = __float2half(v);
        }
    } else {
#pragma unroll
        for (int j = 0; j < 8; j++) h8[j] = __float2half(0.f);
    }
    *(uint4*)(dst + tileoff(row, k, HF / 64)) = *(uint4*)h8;
}

// Wcat[2048,256]: rows 0..1023 = Wfc[:, :256]; rows 1024..2047 = Wfc[:, 256:]
__global__ void k_split_wcat(const float* __restrict__ Wfc,
                             __half* __restrict__ dst) {
    int idx = blockIdx.x * blockDim.x + threadIdx.x;
    if (idx >= 2048 * (HF / 8)) return;
    int o = idx / (HF / 8);
    int k = (idx % (HF / 8)) * 8;
    const float* w = (o < 1024) ? (Wfc + (size_t)o * (2 * HF))
                                : (Wfc + (size_t)(o - 1024) * (2 * HF) + HF);
    const float4* sp = (const float4*)(w + k);
    float4 v0 = sp[0], v1 = sp[1];
    __half h8[8];
    h8[0] = __float2half(v0.x); h8[1] = __float2half(v0.y);
    h8[2] = __float2half(v0.z); h8[3] = __float2half(v0.w);
    h8[4] = __float2half(v1.x); h8[5] = __float2half(v1.y);
    h8[6] = __float2half(v1.z); h8[7] = __float2half(v1.w);
    *(uint4*)(dst + tileoff(o, k, HF / 64)) = *(uint4*)h8;
}

// ---------------- stats / labels ---------------------------------------------
__global__ void k_zero(float* s1, float* q1, float* s2, float* q2,
                       float* cfs, int* cnt) {
    int t = blockIdx.x * blockDim.x + threadIdx.x;
    if (t < HF) { s1[t] = 0.f; q1[t] = 0.f; s2[t] = 0.f; q2[t] = 0.f; }
    if (t < KC) cnt[t] = 0;
    if (t < KC * HF) cfs[t] = 0.f;
}

// Vectorized column stats: thread t owns column group c8 = t&31 (8 cols,
// one uint4 of halfs per row) and row subset rsub = t>>5 (8 rows in flight
// per CTA iteration). Warp reads 512 B of one row per load — fully coalesced,
// 8x fewer LDG than the old 2B-per-thread version, 8x the MLP.
__global__ void k_colstats(const __half* __restrict__ H,
                           float* __restrict__ sum, float* __restrict__ sq) {
    __shared__ float ssum[8][HF];   // 8 KB
    __shared__ float ssq[8][HF];    // 8 KB
    const int t = threadIdx.x;
    const int c8 = t & 31;          // column group (8 cols each)
    const int rsub = t >> 5;        // 0..7
    const int per = (NN + gridDim.x - 1) / gridDim.x;
    const int r0 = blockIdx.x * per;
    const int r1 = min(NN, r0 + per);
    float s[8], q[8];
#pragma unroll
    for (int j = 0; j < 8; j++) { s[j] = 0.f; q[j] = 0.f; }
    for (int r = r0 + rsub; r < r1; r += 8) {
        uint4 raw = *(const uint4*)(H + (size_t)r * HF + c8 * 8);
        const __half* hp = (const __half*)&raw;
#pragma unroll
        for (int j = 0; j < 8; j++) {
            float v = __half2float(hp[j]);
            s[j] += v;
            q[j] = fmaf(v, v, q[j]);
        }
    }
#pragma unroll
    for (int j = 0; j < 8; j++) {
        ssum[rsub][c8 * 8 + j] = s[j];
        ssq[rsub][c8 * 8 + j] = q[j];
    }
    __syncthreads();
    // t = column 0..255: reduce the 8 row-partials, one atomic per column
    float ts = 0.f, tq = 0.f;
#pragma unroll
    for (int i = 0; i < 8; i++) { ts += ssum[i][t]; tq += ssq[i][t]; }
    atomicAdd(&sum[t], ts);
    atomicAdd(&sq[t], tq);
}

__global__ void k_finalize(const float* __restrict__ sum, const float* __restrict__ sq,
                           const float* __restrict__ gam, const float* __restrict__ bet,
                           float* __restrict__ a, float* __restrict__ c) {
    int t = threadIdx.x;
    const float invN = 1.0f / (float)NN;
    float mean = sum[t] * invN;
    float var  = sq[t] * invN - mean * mean;
    float inv  = rsqrtf(var + EPSV);
    float aa   = gam[t] * inv;
    a[t] = aa;
    c[t] = bet[t] - mean * aa;
}

__global__ void k_labels(const float* __restrict__ cid,
                         int* __restrict__ labels, int* __restrict__ cnt) {
    int m = blockIdx.x * blockDim.x + threadIdx.x;
    if (m >= MM) return;
    const float* row = cid + (size_t)m * KC;
    int best = 0;
    float bv = row[0];
#pragma unroll
    for (int k = 1; k < KC; k++) {
        float v = row[k];
        if (v > bv) { bv = v; best = k; }
    }
    labels[m] = best;
    atomicAdd(&cnt[best], 1);
}

// ---------------- fused XC pipeline ------------------------------------------
// v = relu(a2*H2[ci[m]][t] + c2[t]); XCh[tiled(m,t)] = fp16(v);
// acc[lab[m]*HF + t] += v  (smem), then one atomicAdd pass into CFsum.
__global__ void k_xc_fused(const __half* __restrict__ H2,
                           const int* __restrict__ ci,
                           const int* __restrict__ labels,
                           const float* __restrict__ a2,
                           const float* __restrict__ c2,
                           __half* __restrict__ XCh,
                           float* __restrict__ CFsum) {
    __shared__ float acc[KC * HF];   // 40 KB
    const int t = threadIdx.x;
    for (int i = t; i < KC * HF; i += 256) acc[i] = 0.f;
    __syncthreads();
    const float av = a2[t], cv = c2[t];
    const int per = (MMP + gridDim.x - 1) / gridDim.x;
    const int m0 = blockIdx.x * per;
    const int m1 = min(MMP, m0 + per);
    for (int m = m0; m < m1; m++) {
        float v = 0.f;
        if (m < MM) {
            const int r = ci[m];
            v = fmaxf(fmaf(av, __half2float(H2[(size_t)r * HF + t]), cv), 0.f);
            acc[labels[m] * HF + t] += v;
        }
        XCh[tileoff(m, t, HF / 64)] = __float2half(v);
    }
    __syncthreads();
    for (int i = t; i < KC * HF; i += 256) atomicAdd(&CFsum[i], acc[i]);
}

__global__ void k_ptab(const float* __restrict__ Wfc, const float* __restrict__ bfc,
                       const float* __restrict__ CFsum, const int* __restrict__ cnt,
                       float* __restrict__ PA, float* __restrict__ PB) {
    __shared__ float cf[HF];
    int k = blockIdx.y;
    int t = threadIdx.x;
    float cnv = (float)cnt[k];
    cf[t] = CFsum[k * HF + t] / cnv;
    __syncthreads();
    int o = blockIdx.x * 256 + t;
    const float* w = Wfc + (size_t)o * (2 * HF);
    float sa = 0.f, sb = 0.f;
#pragma unroll 4
    for (int j = 0; j < HF; j++) {
        float c = cf[j];
        sa = fmaf(c, w[j], sa);
        sb = fmaf(c, w[HF + j], sb);
    }
    float bb = bfc[o];
    PA[k * O2 + o] = sa + bb;
    PB[k * O2 + o] = sb + bb;
}

// ---------------- host launcher ---------------------------------------------
extern "C" void kernel_launch(void* const* d_in, const int* in_sizes, int n_in,
                              void* d_out, int out_size) {
    const float* x    = (const float*)d_in[0];
    const float* cid  = (const float*)d_in[1];
    const int*   cidx = (const int*)  d_in[2];
    const float* W1   = (const float*)d_in[3];
    const float* b1   = (const float*)d_in[4];
    const float* g1   = (const float*)d_in[5];
    const float* be1  = (const float*)d_in[6];
    const float* W2   = (const float*)d_in[7];
    const float* b2   = (const float*)d_in[8];
    const float* g2   = (const float*)d_in[9];
    const float* be2  = (const float*)d_in[10];
    const float* Wfc  = (const float*)d_in[11];
    const float* bfc  = (const float*)d_in[12];
    float* out = (float*)d_out;

    static bool inited = false;
    static float *sum1, *sq1, *a1, *c1, *sum2, *sq2, *a2, *c2, *CFs, *PA, *PB;
    static int *cnt, *labs;
    static __half *H1, *H2, *xh, *W1h, *A2h, *W2h, *XCh, *WCh;
    if (!inited) {
        inited = true;
        cudaGetSymbolAddress((void**)&H1,   g_H1);
        cudaGetSymbolAddress((void**)&H2,   g_H2);
        cudaGetSymbolAddress((void**)&sum1, g_sum1);
        cudaGetSymbolAddress((void**)&sq1,  g_sq1);
        cudaGetSymbolAddress((void**)&a1,   g_a1);
        cudaGetSymbolAddress((void**)&c1,   g_c1);
        cudaGetSymbolAddress((void**)&sum2, g_sum2);
        cudaGetSymbolAddress((void**)&sq2,  g_sq2);
        cudaGetSymbolAddress((void**)&a2,   g_a2);
        cudaGetSymbolAddress((void**)&c2,   g_c2);
        cudaGetSymbolAddress((void**)&CFs,  g_CFsum);
        cudaGetSymbolAddress((void**)&PA,   g_PA);
        cudaGetSymbolAddress((void**)&PB,   g_PB);
        cudaGetSymbolAddress((void**)&cnt,  g_counts);
        cudaGetSymbolAddress((void**)&labs, g_labels);
        cudaGetSymbolAddress((void**)&xh,   g_xh);
        cudaGetSymbolAddress((void**)&W1h,  g_W1h);
        cudaGetSymbolAddress((void**)&A2h,  g_A2h);
        cudaGetSymbolAddress((void**)&W2h,  g_W2h);
        cudaGetSymbolAddress((void**)&XCh,  g_XCh);
        cudaGetSymbolAddress((void**)&WCh,  g_WCh);
        cudaFuncSetAttribute(k_bulkmma<0>,
                             cudaFuncAttributeMaxDynamicSharedMemorySize, SMEM_GG);
        cudaFuncSetAttribute(k_bulkmma<1>,
                             cudaFuncAttributeMaxDynamicSharedMemorySize, SMEM_GG);
    }

    // Launch order keeps GEMM1 in the ncu-profiled slot (4th launch).
    // 0) zero accumulators
    k_zero<<<40, 256>>>(sum1, sq1, sum2, sq2, CFs, cnt);

    // 1) x -> tiled fp16 (rows padded to NNP, K padded to 512)
    {
        long long t = (long long)NNP * (KP1 / 8);
        k_split_a<<<(int)((t + 255) / 256), 256>>>(x, xh,
                                                   NN, D_IN, KP1 / 8, KP1 / 64, t);
    }
    // 2) W1 -> tiled fp16
    {
        long long t1 = (long long)HF * (KP1 / 8);
        k_split_a<<<cdiv_h((int)t1, 256), 256>>>(W1, W1h,
                                                 HF, D_IN, KP1 / 8, KP1 / 64, t1);
    }
    // 3) GEMM1: H1 = fp16(x @ W1^T + b1)        <-- ncu-profiled launch
    {
        dim3 grid(HF / 128, NNP / 128);
        k_bulkmma<0><<<grid, 256, SMEM_GG>>>(xh, W1h,
            NN, HF, KP1 / 64, b1, H1, nullptr, nullptr, nullptr, nullptr);
    }
    // 4) BN1 stats (vectorized)
    k_colstats<<<512, 256>>>(H1, sum1, sq1);
    k_finalize<<<1, 256>>>(sum1, sq1, g1, be1, a1, c1);

    // 5) W2 -> tiled fp16; A2 = relu(a1*H1 + c1); GEMM2
    {
        long long t2 = (long long)HF * (HF / 8);
        k_split_a<<<cdiv_h((int)t2, 256), 256>>>(W2, W2h,
                                                 HF, HF, HF / 8, HF / 64, t2);
        long long t = (long long)NNP * (HF / 8);
        k_split_aff_a<<<(int)((t + 255) / 256), 256>>>(H1, a1, c1, A2h, NN, t);
        dim3 grid(HF / 128, NNP / 128);
        k_bulkmma<0><<<grid, 256, SMEM_GG>>>(A2h, W2h,
            NN, HF, HF / 64, b2, H2, nullptr, nullptr, nullptr, nullptr);
    }
    // 6) BN2 stats (vectorized)
    k_colstats<<<512, 256>>>(H2, sum2, sq2);
    k_finalize<<<1, 256>>>(sum2, sq2, g2, be2, a2, c2);

    // 7) labels + counts
    k_labels<<<cdiv_h(MM, 256), 256>>>(cid, labs, cnt);

    // 8) fused: XCh (tiled fp16) + cluster feature sums
    k_xc_fused<<<256, 256>>>(H2, cidx, labs, a2, c2, XCh, CFs);

    // 9) Wcat -> tiled fp16; PA/PB tables (fp32, exact)
    k_split_wcat<<<cdiv_h(2048 * (HF / 8), 256), 256>>>(Wfc, WCh);
    {
        dim3 grid(O2 / 256, KC);
        k_ptab<<<grid, 256>>>(Wfc, bfc, CFs, cnt, PA, PB);
    }

    // 10) final GEMM: Y = XC @ Wcat^T, epilogue adds PB/PA, scatters rows
    {
        dim3 grid(2048 / 128, MMP / 128);
        k_bulkmma<1><<<grid, 256, SMEM_GG>>>(XCh, WCh,
            MM, 2048, HF / 64, nullptr, nullptr, labs, PA, PB, out);
    }
}